// round 12
// baseline (speedup 1.0000x reference)
#include <cuda_runtime.h>
#include <cuda_fp16.h>
#include <cstdint>

// ---------------- problem shape ----------------
static constexpr int B_ = 8;
static constexpr int T_ = 2048;
static constexpr int C_ = 1024;
static constexpr int H_ = 1024;

// ---------------- scratch (__device__ globals) ----------------
// fp16 hi/lo arrays, PAIR-PERMUTED along the contraction dim (4x4 pair
// transpose within each 32-elem K-block; involution; applied to both operands).
__device__ __half g_xh[(size_t)B_ * T_ * C_];
__device__ __half g_xl[(size_t)B_ * T_ * C_];
__device__ __half g_wqth[(size_t)C_ * H_];   // Wq^T [C,H], permuted along H
__device__ __half g_wqtl[(size_t)C_ * H_];
__device__ __half g_wkth[(size_t)C_ * H_];
__device__ __half g_wktl[(size_t)C_ * H_];
__device__ float  g_mtp[(size_t)4 * C_ * C_];  // Mt split-K partials (fp32)
__device__ __half g_mth[(size_t)C_ * C_];      // Mt hi/lo, permuted along c
__device__ __half g_mtl[(size_t)C_ * C_];
__device__ __half g_uh[(size_t)B_ * T_ * C_];  // u = x·M, permuted along c'
__device__ __half g_ul[(size_t)B_ * T_ * C_];
__device__ __half g_wvh[(size_t)H_ * C_];
__device__ __half g_vth[(size_t)B_ * H_ * T_];   // v^T [b][h][t], hi only
__device__ __half g_weih[(size_t)B_ * T_ * T_];  // wei fp16 hi only

// ---------------- helpers ----------------
__device__ __forceinline__ uint32_t pack2(__half a, __half b) {
    __half2 h2 = __halves2half2(a, b);
    return *reinterpret_cast<uint32_t*>(&h2);
}
__device__ __forceinline__ void cpa16(uint32_t dst, const void* src) {
    asm volatile("cp.async.cg.shared.global [%0], [%1], 16;" :: "r"(dst), "l"(src));
}
__device__ __forceinline__ void cp_commit() {
    asm volatile("cp.async.commit_group;" ::: "memory");
}
template <int N>
__device__ __forceinline__ void cp_wait() {
    asm volatile("cp.async.wait_group %0;" :: "n"(N) : "memory");
}
__device__ __forceinline__ uint32_t smem_u32(const void* p) {
    uint32_t a;
    asm("{ .reg .u64 t; cvta.to.shared.u64 t, %1; cvt.u32.u64 %0, t; }" : "=r"(a) : "l"(p));
    return a;
}
// D(f32) += A*B, m16n8k16 fp16 inputs
__device__ __forceinline__ void mma16(float* d, uint32_t a0, uint32_t a1, uint32_t a2,
                                      uint32_t a3, uint32_t b0, uint32_t b1) {
    asm volatile(
        "mma.sync.aligned.m16n8k16.row.col.f32.f16.f16.f32 "
        "{%0,%1,%2,%3},{%4,%5,%6,%7},{%8,%9},{%0,%1,%2,%3};"
        : "+f"(d[0]), "+f"(d[1]), "+f"(d[2]), "+f"(d[3])
        : "r"(a0), "r"(a1), "r"(a2), "r"(a3), "r"(b0), "r"(b1));
}
// D(f16) += A*B, m16n8k16, fp16 accumulator (2 regs: {c0,c1},{c2,c3})
__device__ __forceinline__ void mma16h(uint32_t* d, uint32_t a0, uint32_t a1, uint32_t a2,
                                       uint32_t a3, uint32_t b0, uint32_t b1) {
    asm volatile(
        "mma.sync.aligned.m16n8k16.row.col.f16.f16.f16.f16 "
        "{%0,%1},{%2,%3,%4,%5},{%6,%7},{%0,%1};"
        : "+r"(d[0]), "+r"(d[1])
        : "r"(a0), "r"(a1), "r"(a2), "r"(a3), "r"(b0), "r"(b1));
}
// permuted element index within 32-block (pair-level 4x4 transpose; involution)
__device__ __forceinline__ int pperm(int c) {
    const int p = (c & 31) >> 1;
    const int pp = ((p & 3) << 2) | (p >> 2);
    return (c & ~31) | (pp << 1) | (c & 1);
}

// ---------------- FP16 multi-pass NT GEMM via mma.sync (pair-permuted operands) ----------------
// C[m,n] = alpha * sum_k A[m,k]*B[n,k]. CTA 128x128, BK=32, 256 thr (2x4 warps).
// PASSES=3: AhBh (f32 acc) + AlBh + AhBl (both in a dedicated f16 accumulator —
//           corrections are small-magnitude; f16 acc runs at the fast HMMA rate).
// PASSES=1: AhBh only (f32 acc).
// EPI=0: Cf = fp32*alpha (linear cols). EPI=1: Ch/Cl fp16 hi/lo (permuted cols).
// EPI=2: Ch fp16 hi only (permuted cols).
// causal: 0 none; 1 skip block if bn>bm; 2 Keff=min(K,(bm+1)*128), heavy-first bm remap.
static constexpr int GEMM_SMEM = 2 * 32768;   // 64 KB double buffer

template <int EPI, int PASSES>
__global__ __launch_bounds__(256, 2)
void mma_nt(const __half* __restrict__ Ahi, const __half* __restrict__ Alo,
            const __half* __restrict__ Bhi, const __half* __restrict__ Blo,
            float* __restrict__ Cf, __half* __restrict__ Ch, __half* __restrict__ Cl,
            int K, int lda, int ldb, int ldc,
            long long sA, long long sB, long long sC,
            float alpha, int causal)
{
    extern __shared__ char smc[];
    const int bn = blockIdx.x, bz = blockIdx.z;
    int bm = blockIdx.y;
    if (causal == 1 && bn > bm) return;
    if (causal == 2) bm = gridDim.y - 1 - bm;     // heavy tiles first
    int Keff = K;
    if (causal == 2) { int kl = (bm + 1) * 128; Keff = kl < K ? kl : K; }
    const int nk = Keff / 32;

    const __half* Ah = Ahi + (size_t)bz * sA;
    const __half* Al = (PASSES >= 2) ? Alo + (size_t)bz * sA : nullptr;
    const __half* Bh = Bhi + (size_t)bz * sB;
    const __half* Bl = (PASSES == 3) ? Blo + (size_t)bz * sB : nullptr;

    const int tid = threadIdx.x;
    const int lane = tid & 31, w = tid >> 5;
    const int wm = w & 1, wn = w >> 1;            // 2 (M) x 4 (N) warp grid
    const int gr = lane >> 2, tc = lane & 3;
    const uint32_t sbase = smem_u32(smc);

    // stage loader: arrays of [128][32] halves (64B rows); 512 16B-chunks each.
    auto load_stage = [&](int kt, int s) {
        const int k0 = kt * 32;
        const uint32_t dst = sbase + (uint32_t)s * 32768u;
#pragma unroll
        for (int t = 0; t < 2; t++) {
            const int idx = t * 256 + tid;         // 0..511
            const int row = idx >> 2, j = (idx & 3) * 8;
            const uint32_t off = (uint32_t)(row * 64 + j * 2);
            const size_t ga = (size_t)(bm * 128 + row) * lda + k0 + j;
            const size_t gb = (size_t)(bn * 128 + row) * ldb + k0 + j;
            cpa16(dst + off,           Ah + ga);
            if (PASSES >= 2) cpa16(dst + 8192u + off, Al + ga);
            cpa16(dst + 16384u + off,  Bh + gb);
            if (PASSES == 3) cpa16(dst + 24576u + off, Bl + gb);
        }
        cp_commit();
    };

    float acc[4][4][4];
#pragma unroll
    for (int i = 0; i < 4; i++)
#pragma unroll
        for (int j = 0; j < 4; j++)
#pragma unroll
            for (int r = 0; r < 4; r++) acc[i][j][r] = 0.f;

    uint32_t acc16[4][4][2];                      // f16 correction accumulator
#pragma unroll
    for (int i = 0; i < 4; i++)
#pragma unroll
        for (int j = 0; j < 4; j++) { acc16[i][j][0] = 0u; acc16[i][j][1] = 0u; }

    load_stage(0, 0);

    const int rbA = (wm * 64 + gr) * 4 + tc;       // uint4 index of A frag row
    const int rbB = (wn * 32 + gr) * 4 + tc;

    for (int kt = 0; kt < nk; kt++) {
        const int s = kt & 1;
        cp_wait<0>();
        __syncthreads();                            // data(kt) visible; compute(kt-1) done
        if (kt + 1 < nk) load_stage(kt + 1, s ^ 1); // overlaps compute(kt)

        const uint4* S   = (const uint4*)(smc + s * 32768);
        const uint4* pAh = S;
        const uint4* pAl = S + 512;
        const uint4* pBh = S + 1024;
        const uint4* pBl = S + 1536;

        if (PASSES == 1) {
            uint4 bh0 = pBh[rbB], bh1 = pBh[rbB + 32], bh2 = pBh[rbB + 64], bh3 = pBh[rbB + 96];
#pragma unroll
            for (int fm = 0; fm < 4; fm++) {
                const int ra = rbA + fm * 64;
                uint4 a0 = pAh[ra], a8 = pAh[ra + 32];
#pragma unroll
                for (int fn = 0; fn < 4; fn++) {
                    const uint4 bh = fn == 0 ? bh0 : fn == 1 ? bh1 : fn == 2 ? bh2 : bh3;
                    float* a = acc[fm][fn];
                    mma16(a, a0.x, a8.x, a0.y, a8.y, bh.x, bh.y);
                    mma16(a, a0.z, a8.z, a0.w, a8.w, bh.z, bh.w);
                }
            }
        } else {
            // pass 1+2: hh -> f32 acc, lh -> f16 acc (B frag loaded per fn; not cached)
#pragma unroll
            for (int fm = 0; fm < 4; fm++) {
                const int ra = rbA + fm * 64;
                uint4 a0 = pAh[ra], a8 = pAh[ra + 32];
                uint4 l0 = pAl[ra], l8 = pAl[ra + 32];
#pragma unroll
                for (int fn = 0; fn < 4; fn++) {
                    const uint4 bh = pBh[rbB + fn * 32];
                    float* a = acc[fm][fn];
                    uint32_t* c = acc16[fm][fn];
                    mma16(a, a0.x, a8.x, a0.y, a8.y, bh.x, bh.y);
                    mma16h(c, l0.x, l8.x, l0.y, l8.y, bh.x, bh.y);
                    mma16(a, a0.z, a8.z, a0.w, a8.w, bh.z, bh.w);
                    mma16h(c, l0.z, l8.z, l0.w, l8.w, bh.z, bh.w);
                }
            }
            // pass 3: hl -> f16 acc
#pragma unroll
            for (int fm = 0; fm < 4; fm++) {
                const int ra = rbA + fm * 64;
                uint4 a0 = pAh[ra], a8 = pAh[ra + 32];
#pragma unroll
                for (int fn = 0; fn < 4; fn++) {
                    const uint4 bl = pBl[rbB + fn * 32];
                    uint32_t* c = acc16[fm][fn];
                    mma16h(c, a0.x, a8.x, a0.y, a8.y, bl.x, bl.y);
                    mma16h(c, a0.z, a8.z, a0.w, a8.w, bl.z, bl.w);
                }
            }
        }
    }

    // ---- epilogue ----
#pragma unroll
    for (int fm = 0; fm < 4; fm++) {
        const int r0 = bm * 128 + wm * 64 + fm * 16 + gr;
#pragma unroll
        for (int fn = 0; fn < 4; fn++) {
            const int c0 = bn * 128 + wn * 32 + fn * 8 + 2 * tc;
            const size_t b0 = (size_t)bz * sC + (size_t)r0 * ldc;
            const size_t b8 = b0 + (size_t)8 * ldc;
            float* a = acc[fm][fn];
            if (PASSES == 3) {                      // fold f16 corrections into f32 acc
                float2 c01 = __half22float2(*reinterpret_cast<__half2*>(&acc16[fm][fn][0]));
                float2 c23 = __half22float2(*reinterpret_cast<__half2*>(&acc16[fm][fn][1]));
                a[0] += c01.x; a[1] += c01.y; a[2] += c23.x; a[3] += c23.y;
            }
            if (EPI == 0) {
                *(float2*)(Cf + b0 + c0) = make_float2(a[0] * alpha, a[1] * alpha);
                *(float2*)(Cf + b8 + c0) = make_float2(a[2] * alpha, a[3] * alpha);
            } else {
                const int cp = pperm(c0);
                __half h0 = __float2half_rn(a[0]), h1 = __float2half_rn(a[1]);
                __half h2 = __float2half_rn(a[2]), h3 = __float2half_rn(a[3]);
                *(__half2*)(Ch + b0 + cp) = __halves2half2(h0, h1);
                *(__half2*)(Ch + b8 + cp) = __halves2half2(h2, h3);
                if (EPI == 1) {
                    *(__half2*)(Cl + b0 + cp) = __halves2half2(
                        __float2half_rn(a[0] - __half2float(h0)),
                        __float2half_rn(a[1] - __half2float(h1)));
                    *(__half2*)(Cl + b8 + cp) = __halves2half2(
                        __float2half_rn(a[2] - __half2float(h2)),
                        __float2half_rn(a[3] - __half2float(h3)));
                }
            }
        }
    }
}

// ---------------- elementwise fp16 split, pair-permuted layout ----------------
__global__ void split_kernel(const float* __restrict__ src,
                             __half* __restrict__ hi, __half* __restrict__ lo, int n8)
{
    const int i = blockIdx.x * blockDim.x + threadIdx.x;
    if (i >= n8) return;
    const int u = i & 3;
    const int blk = (i >> 2) * 32;
    uint32_t ho[4], lw[4];
#pragma unroll
    for (int b = 0; b < 4; b++) {
        const float2 v = *(const float2*)(src + blk + 8 * b + 2 * u);
        __half h0 = __float2half_rn(v.x), h1 = __float2half_rn(v.y);
        ho[b] = pack2(h0, h1);
        lw[b] = pack2(__float2half_rn(v.x - __half2float(h0)),
                      __float2half_rn(v.y - __half2float(h1)));
    }
    ((uint2*)(hi + blk))[u * 2 + 0] = make_uint2(ho[0], ho[1]);
    ((uint2*)(hi + blk))[u * 2 + 1] = make_uint2(ho[2], ho[3]);
    if (lo) {
        ((uint2*)(lo + blk))[u * 2 + 0] = make_uint2(lw[0], lw[1]);
        ((uint2*)(lo + blk))[u * 2 + 1] = make_uint2(lw[2], lw[3]);
    }
}

// ---------------- Mt split-K reduce + permuted fp16 hi/lo split ----------------
__global__ void mt_reduce_split(const float* __restrict__ p,
                                __half* __restrict__ hi, __half* __restrict__ lo, int n8)
{
    const int i = blockIdx.x * blockDim.x + threadIdx.x;
    if (i >= n8) return;
    const size_t CC = (size_t)C_ * C_;
    const int u = i & 3;
    const int blk = (i >> 2) * 32;
    uint32_t ho[4], lw[4];
#pragma unroll
    for (int b = 0; b < 4; b++) {
        const size_t o = (size_t)blk + 8 * b + 2 * u;
        float2 v0 = *(const float2*)(p + o);
        float2 v1 = *(const float2*)(p + CC + o);
        float2 v2 = *(const float2*)(p + 2 * CC + o);
        float2 v3 = *(const float2*)(p + 3 * CC + o);
        float x = (v0.x + v1.x) + (v2.x + v3.x);
        float y = (v0.y + v1.y) + (v2.y + v3.y);
        __half h0 = __float2half_rn(x), h1 = __float2half_rn(y);
        ho[b] = pack2(h0, h1);
        lw[b] = pack2(__float2half_rn(x - __half2float(h0)),
                      __float2half_rn(y - __half2float(h1)));
    }
    ((uint2*)(hi + blk))[u * 2 + 0] = make_uint2(ho[0], ho[1]);
    ((uint2*)(hi + blk))[u * 2 + 1] = make_uint2(ho[2], ho[3]);
    ((uint2*)(lo + blk))[u * 2 + 0] = make_uint2(lw[0], lw[1]);
    ((uint2*)(lo + blk))[u * 2 + 1] = make_uint2(lw[2], lw[3]);
}

// ---------------- transpose + fp16 split: W[H,C] -> Wt hi/lo [C,H], permuted along H ----------------
__global__ __launch_bounds__(256)
void transpose_split_kernel(const float* __restrict__ W,
                            __half* __restrict__ th, __half* __restrict__ tl,
                            int Hd, int Cd)
{
    __shared__ float tile[64][33];
    const int c0 = blockIdx.x * 32, h0 = blockIdx.y * 64;
    const int tid = threadIdx.x;
    {
        const int lc = tid & 31;
        const int lh = tid >> 5;
#pragma unroll
        for (int i = 0; i < 8; i++)
            tile[lh + 8 * i][lc] = W[(size_t)(h0 + lh + 8 * i) * Cd + c0 + lc];
    }
    __syncthreads();
    const int lc = tid >> 3;
    const int lp = tid & 7;
#pragma unroll
    for (int i = 0; i < 4; i++) {
        const int p = lp + 8 * i;
        const int b = p >> 4;
        const int pin = p & 15;
        const int ppin = ((pin & 3) << 2) | (pin >> 2);
        const int hs = p * 2;
        const float v0 = tile[hs][lc], v1 = tile[hs + 1][lc];
        const __half h0_ = __float2half_rn(v0), h1_ = __float2half_rn(v1);
        const size_t o = (size_t)(c0 + lc) * Hd + h0 + b * 32 + ppin * 2;
        *(__half2*)(th + o) = __halves2half2(h0_, h1_);
        *(__half2*)(tl + o) = __halves2half2(__float2half_rn(v0 - __half2float(h0_)),
                                             __float2half_rn(v1 - __half2float(h1_)));
    }
}

// ---------------- single-sweep causal softmax + fp16 hi write (permuted cols) ----------------
__global__ __launch_bounds__(256)
void softmax_split_kernel(float* __restrict__ W, __half* __restrict__ Wh, int T)
{
    const long long row = blockIdx.x;
    const int t = (int)(row % T);
    float* p   = W  + row * (long long)T;
    __half* ph = Wh + row * (long long)T;
    const int n = t + 1;
    const int tid = threadIdx.x;
    const int base = tid * 8;

    __shared__ float red[8];

    float v[8];
    {
        float4 a = *(const float4*)(p + base);
        float4 b = *(const float4*)(p + base + 4);
        v[0] = a.x; v[1] = a.y; v[2] = a.z; v[3] = a.w;
        v[4] = b.x; v[5] = b.y; v[6] = b.z; v[7] = b.w;
    }
#pragma unroll
    for (int j = 0; j < 8; j++)
        if (base + j >= n) v[j] = -3.4e38f;

    float m = v[0];
#pragma unroll
    for (int j = 1; j < 8; j++) m = fmaxf(m, v[j]);
#pragma unroll
    for (int o = 16; o; o >>= 1) m = fmaxf(m, __shfl_xor_sync(0xffffffffu, m, o));
    if ((tid & 31) == 0) red[tid >> 5] = m;
    __syncthreads();
    if (tid < 32) {
        float mb = (tid < 8) ? red[tid] : -3.4e38f;
#pragma unroll
        for (int o = 4; o; o >>= 1) mb = fmaxf(mb, __shfl_xor_sync(0xffffffffu, mb, o));
        if (tid == 0) red[0] = mb;
    }
    __syncthreads();
    m = red[0];
    __syncthreads();

    float s = 0.f;
#pragma unroll
    for (int j = 0; j < 8; j++) {
        v[j] = (base + j < n) ? expf(v[j] - m) : 0.f;
        s += v[j];
    }
#pragma unroll
    for (int o = 16; o; o >>= 1) s += __shfl_xor_sync(0xffffffffu, s, o);
    if ((tid & 31) == 0) red[tid >> 5] = s;
    __syncthreads();
    if (tid < 32) {
        float sb = (tid < 8) ? red[tid] : 0.f;
#pragma unroll
        for (int o = 4; o; o >>= 1) sb += __shfl_xor_sync(0xffffffffu, sb, o);
        if (tid == 0) red[0] = sb;
    }
    __syncthreads();
    const float inv = 1.f / red[0];

#pragma unroll
    for (int j = 0; j < 8; j++) v[j] *= inv;
    *(float4*)(p + base)     = make_float4(v[0], v[1], v[2], v[3]);
    *(float4*)(p + base + 4) = make_float4(v[4], v[5], v[6], v[7]);

    const int u = tid & 3;
    __half* phb = ph + (base & ~31);
#pragma unroll
    for (int b = 0; b < 4; b++) {
        *(__half2*)(phb + (b * 4 + u) * 2) =
            __halves2half2(__float2half_rn(v[2 * b]), __float2half_rn(v[2 * b + 1]));
    }
}

// ---------------- launch ----------------
extern "C" void kernel_launch(void* const* d_in, const int* in_sizes, int n_in,
                              void* d_out, int out_size)
{
    (void)in_sizes; (void)n_in; (void)out_size;
    const float* x  = (const float*)d_in[0];
    const float* Wk = (const float*)d_in[1];
    const float* Wq = (const float*)d_in[2];
    const float* Wv = (const float*)d_in[3];

    float* out = (float*)d_out;                      // [B, T, H]
    float* wei = out + (size_t)B_ * T_ * H_;         // [B, T, T]

    __half *xh, *xl, *wqth, *wqtl, *wkth, *wktl, *mth, *mtl, *uh, *ul, *wvh, *vth, *weih;
    float* mtp;
    cudaGetSymbolAddress((void**)&xh, g_xh);     cudaGetSymbolAddress((void**)&xl, g_xl);
    cudaGetSymbolAddress((void**)&wqth, g_wqth); cudaGetSymbolAddress((void**)&wqtl, g_wqtl);
    cudaGetSymbolAddress((void**)&wkth, g_wkth); cudaGetSymbolAddress((void**)&wktl, g_wktl);
    cudaGetSymbolAddress((void**)&mtp, g_mtp);
    cudaGetSymbolAddress((void**)&mth, g_mth);   cudaGetSymbolAddress((void**)&mtl, g_mtl);
    cudaGetSymbolAddress((void**)&uh, g_uh);     cudaGetSymbolAddress((void**)&ul, g_ul);
    cudaGetSymbolAddress((void**)&wvh, g_wvh);
    cudaGetSymbolAddress((void**)&vth, g_vth);
    cudaGetSymbolAddress((void**)&weih, g_weih);

    cudaFuncSetAttribute(mma_nt<0,3>, cudaFuncAttributeMaxDynamicSharedMemorySize, GEMM_SMEM);
    cudaFuncSetAttribute(mma_nt<1,3>, cudaFuncAttributeMaxDynamicSharedMemorySize, GEMM_SMEM);
    cudaFuncSetAttribute(mma_nt<2,1>, cudaFuncAttributeMaxDynamicSharedMemorySize, GEMM_SMEM);
    cudaFuncSetAttribute(mma_nt<0,1>, cudaFuncAttributeMaxDynamicSharedMemorySize, GEMM_SMEM);

    const dim3 blk(256);

    // 1) splits: x -> hi/lo; Wv -> hi; Wq/Wk -> transposed hi/lo (permuted along H)
    {
        const int n8x = (B_ * T_ * C_) / 8;
        split_kernel<<<(n8x + 255) / 256, 256>>>(x, xh, xl, n8x);
        const int n8w = (H_ * C_) / 8;
        split_kernel<<<(n8w + 255) / 256, 256>>>(Wv, wvh, nullptr, n8w);
        const dim3 gt(C_ / 32, H_ / 64);
        transpose_split_kernel<<<gt, blk>>>(Wq, wqth, wqtl, H_, C_);
        transpose_split_kernel<<<gt, blk>>>(Wk, wkth, wktl, H_, C_);
    }

    // 2) Mt partials via split-K=4, then reduce + permuted fp16 hi/lo split.
    {
        const dim3 g(C_ / 128, C_ / 128, 4);
        mma_nt<0,3><<<g, blk, GEMM_SMEM>>>(wkth, wktl, wqth, wqtl, mtp, nullptr, nullptr,
                                           256, H_, H_, C_,
                                           256, 256, (long long)C_ * C_, 1.f, 0);
        mt_reduce_split<<<(C_ * C_ / 8 + 255) / 256, 256>>>(mtp, mth, mtl, C_ * C_ / 8);
    }

    // 3) v: vT[b,h,t] = Wv_h[h,:]·x_h[b,t,:], 1-pass, hi-only
    {
        const dim3 g(T_ / 128, H_ / 128, B_);
        mma_nt<2,1><<<g, blk, GEMM_SMEM>>>(wvh, nullptr, xh, nullptr, nullptr, vth, nullptr,
                                           C_, C_, C_, T_,
                                           0, (long long)T_ * C_, (long long)H_ * T_, 1.f, 0);
    }

    // 4) u[m,c'] = sum_c x[m,c]·Mt[c',c], 3-pass, hi/lo out
    {
        const dim3 g(C_ / 128, (B_ * T_) / 128, 1);
        mma_nt<1,3><<<g, blk, GEMM_SMEM>>>(xh, xl, mth, mtl, nullptr, uh, ul,
                                           C_, C_, C_, C_, 0, 0, 0, 1.f, 0);
    }

    // 5) logits: wei[b,t,s] = (1/32) sum_c' u·x, 3-pass, causal block skip
    {
        const dim3 g(T_ / 128, T_ / 128, B_);
        mma_nt<0,3><<<g, blk, GEMM_SMEM>>>(uh, ul, xh, xl, wei, nullptr, nullptr,
                                           C_, C_, C_, T_,
                                           (long long)T_ * C_, (long long)T_ * C_,
                                           (long long)T_ * T_, 0.03125f, 1);
    }

    // 6) single-sweep causal softmax + permuted fp16 hi of wei
    softmax_split_kernel<<<B_ * T_, 256>>>(wei, weih, T_);

    // 7) out = wei_h · vT_h, 1-pass, causal K, heavy-first
    {
        const dim3 g(H_ / 128, T_ / 128, B_);
        mma_nt<0,1><<<g, blk, GEMM_SMEM>>>(weih, nullptr, vth, nullptr, out, nullptr, nullptr,
                                           T_, T_, T_, H_,
                                           (long long)T_ * T_, (long long)H_ * T_,
                                           (long long)T_ * H_, 1.f, 2);
    }
}

// round 13
// speedup vs baseline: 1.2341x; 1.2341x over previous
#include <cuda_runtime.h>
#include <cuda_fp16.h>
#include <cstdint>

// ---------------- problem shape ----------------
static constexpr int B_ = 8;
static constexpr int T_ = 2048;
static constexpr int C_ = 1024;
static constexpr int H_ = 1024;

// ---------------- scratch (__device__ globals) ----------------
// fp16 hi/lo arrays, PAIR-PERMUTED along the contraction dim (4x4 pair
// transpose within each 32-elem K-block; involution; applied to both operands).
__device__ __half g_xh[(size_t)B_ * T_ * C_];
__device__ __half g_xl[(size_t)B_ * T_ * C_];
__device__ __half g_wqth[(size_t)C_ * H_];   // Wq^T [C,H], permuted along H
__device__ __half g_wqtl[(size_t)C_ * H_];
__device__ __half g_wkth[(size_t)C_ * H_];
__device__ __half g_wktl[(size_t)C_ * H_];
__device__ float  g_mtp[(size_t)4 * C_ * C_];  // Mt split-K partials (fp32)
__device__ __half g_mth[(size_t)C_ * C_];      // Mt hi/lo, permuted along c
__device__ __half g_mtl[(size_t)C_ * C_];
__device__ __half g_uh[(size_t)B_ * T_ * C_];  // u = x·M, permuted along c'
__device__ __half g_ul[(size_t)B_ * T_ * C_];
__device__ __half g_wvh[(size_t)H_ * C_];
__device__ __half g_vth[(size_t)B_ * H_ * T_];   // v^T [b][h][t], hi only
__device__ __half g_weih[(size_t)B_ * T_ * T_];  // wei fp16 hi only

// ---------------- helpers ----------------
__device__ __forceinline__ uint32_t pack2(__half a, __half b) {
    __half2 h2 = __halves2half2(a, b);
    return *reinterpret_cast<uint32_t*>(&h2);
}
__device__ __forceinline__ void cpa16(uint32_t dst, const void* src) {
    asm volatile("cp.async.cg.shared.global [%0], [%1], 16;" :: "r"(dst), "l"(src));
}
__device__ __forceinline__ void cp_commit() {
    asm volatile("cp.async.commit_group;" ::: "memory");
}
template <int N>
__device__ __forceinline__ void cp_wait() {
    asm volatile("cp.async.wait_group %0;" :: "n"(N) : "memory");
}
__device__ __forceinline__ uint32_t smem_u32(const void* p) {
    uint32_t a;
    asm("{ .reg .u64 t; cvta.to.shared.u64 t, %1; cvt.u32.u64 %0, t; }" : "=r"(a) : "l"(p));
    return a;
}
// D += A*B, m16n8k16 fp16 inputs, fp32 accum
__device__ __forceinline__ void mma16(float* d, uint32_t a0, uint32_t a1, uint32_t a2,
                                      uint32_t a3, uint32_t b0, uint32_t b1) {
    asm volatile(
        "mma.sync.aligned.m16n8k16.row.col.f32.f16.f16.f32 "
        "{%0,%1,%2,%3},{%4,%5,%6,%7},{%8,%9},{%0,%1,%2,%3};"
        : "+f"(d[0]), "+f"(d[1]), "+f"(d[2]), "+f"(d[3])
        : "r"(a0), "r"(a1), "r"(a2), "r"(a3), "r"(b0), "r"(b1));
}
// permuted element index within 32-block (pair-level 4x4 transpose; involution)
__device__ __forceinline__ int pperm(int c) {
    const int p = (c & 31) >> 1;
    const int pp = ((p & 3) << 2) | (p >> 2);
    return (c & ~31) | (pp << 1) | (c & 1);
}

// ---------------- FP16 multi-pass NT GEMM tile body (pair-permuted operands) ----------------
// One 128x128 output tile at (bm, bn, bz). BK=32, 256 thr (2x4 warps).
// PASSES=3: AhBh + AlBh + AhBl (all fp32 acc). PASSES=1: AhBh only.
// EPI=0: Cf = fp32*alpha (linear cols). EPI=1: Ch/Cl fp16 hi/lo (permuted cols).
// EPI=2: Ch fp16 hi only (permuted cols).
static constexpr int GEMM_SMEM = 2 * 32768;   // 64 KB double buffer

template <int EPI, int PASSES>
__device__ __forceinline__
void gemm_tile(const __half* __restrict__ Ahi, const __half* __restrict__ Alo,
               const __half* __restrict__ Bhi, const __half* __restrict__ Blo,
               float* __restrict__ Cf, __half* __restrict__ Ch, __half* __restrict__ Cl,
               int K, int lda, int ldb, int ldc,
               long long sA, long long sB, long long sC,
               float alpha, int Keff, int bm, int bn, int bz, char* smc)
{
    const int nk = Keff / 32;

    const __half* Ah = Ahi + (size_t)bz * sA;
    const __half* Al = (PASSES >= 2) ? Alo + (size_t)bz * sA : nullptr;
    const __half* Bh = Bhi + (size_t)bz * sB;
    const __half* Bl = (PASSES == 3) ? Blo + (size_t)bz * sB : nullptr;

    const int tid = threadIdx.x;
    const int lane = tid & 31, w = tid >> 5;
    const int wm = w & 1, wn = w >> 1;            // 2 (M) x 4 (N) warp grid
    const int gr = lane >> 2, tc = lane & 3;
    const uint32_t sbase = smem_u32(smc);

    // stage loader: arrays of [128][32] halves (64B rows); 512 16B-chunks each.
    auto load_stage = [&](int kt, int s) {
        const int k0 = kt * 32;
        const uint32_t dst = sbase + (uint32_t)s * 32768u;
#pragma unroll
        for (int t = 0; t < 2; t++) {
            const int idx = t * 256 + tid;         // 0..511
            const int row = idx >> 2, j = (idx & 3) * 8;
            const uint32_t off = (uint32_t)(row * 64 + j * 2);
            const size_t ga = (size_t)(bm * 128 + row) * lda + k0 + j;
            const size_t gb = (size_t)(bn * 128 + row) * ldb + k0 + j;
            cpa16(dst + off,           Ah + ga);
            if (PASSES >= 2) cpa16(dst + 8192u + off, Al + ga);
            cpa16(dst + 16384u + off,  Bh + gb);
            if (PASSES == 3) cpa16(dst + 24576u + off, Bl + gb);
        }
        cp_commit();
    };

    float acc[4][4][4];
#pragma unroll
    for (int i = 0; i < 4; i++)
#pragma unroll
        for (int j = 0; j < 4; j++)
#pragma unroll
            for (int r = 0; r < 4; r++) acc[i][j][r] = 0.f;

    load_stage(0, 0);

    const int rbA = (wm * 64 + gr) * 4 + tc;       // uint4 index of A frag row
    const int rbB = (wn * 32 + gr) * 4 + tc;

    for (int kt = 0; kt < nk; kt++) {
        const int s = kt & 1;
        cp_wait<0>();
        __syncthreads();                            // data(kt) visible; compute(kt-1) done
        if (kt + 1 < nk) load_stage(kt + 1, s ^ 1); // overlaps compute(kt)

        const uint4* S   = (const uint4*)(smc + s * 32768);
        const uint4* pAh = S;
        const uint4* pAl = S + 512;
        const uint4* pBh = S + 1024;
        const uint4* pBl = S + 1536;

        uint4 bh0 = pBh[rbB], bh1 = pBh[rbB + 32], bh2 = pBh[rbB + 64], bh3 = pBh[rbB + 96];

#pragma unroll
        for (int fm = 0; fm < 4; fm++) {
            const int ra = rbA + fm * 64;
            uint4 a0 = pAh[ra], a8 = pAh[ra + 32];
            uint4 l0, l8;
            if (PASSES >= 2) { l0 = pAl[ra]; l8 = pAl[ra + 32]; }
#pragma unroll
            for (int fn = 0; fn < 4; fn++) {
                const uint4 bh = fn == 0 ? bh0 : fn == 1 ? bh1 : fn == 2 ? bh2 : bh3;
                float* a = acc[fm][fn];
                mma16(a, a0.x, a8.x, a0.y, a8.y, bh.x, bh.y);
                if (PASSES >= 2) mma16(a, l0.x, l8.x, l0.y, l8.y, bh.x, bh.y);
                mma16(a, a0.z, a8.z, a0.w, a8.w, bh.z, bh.w);
                if (PASSES >= 2) mma16(a, l0.z, l8.z, l0.w, l8.w, bh.z, bh.w);
            }
        }

        if (PASSES == 3) {
            uint4 bl0 = pBl[rbB], bl1 = pBl[rbB + 32], bl2 = pBl[rbB + 64], bl3 = pBl[rbB + 96];
#pragma unroll
            for (int fm = 0; fm < 4; fm++) {
                const int ra = rbA + fm * 64;
                uint4 a0 = pAh[ra], a8 = pAh[ra + 32];
#pragma unroll
                for (int fn = 0; fn < 4; fn++) {
                    const uint4 bl = fn == 0 ? bl0 : fn == 1 ? bl1 : fn == 2 ? bl2 : bl3;
                    float* a = acc[fm][fn];
                    mma16(a, a0.x, a8.x, a0.y, a8.y, bl.x, bl.y);
                    mma16(a, a0.z, a8.z, a0.w, a8.w, bl.z, bl.w);
                }
            }
        }
    }

    // ---- epilogue ----
#pragma unroll
    for (int fm = 0; fm < 4; fm++) {
        const int r0 = bm * 128 + wm * 64 + fm * 16 + gr;
#pragma unroll
        for (int fn = 0; fn < 4; fn++) {
            const int c0 = bn * 128 + wn * 32 + fn * 8 + 2 * tc;
            const size_t b0 = (size_t)bz * sC + (size_t)r0 * ldc;
            const size_t b8 = b0 + (size_t)8 * ldc;
            const float* a = acc[fm][fn];
            if (EPI == 0) {
                *(float2*)(Cf + b0 + c0) = make_float2(a[0] * alpha, a[1] * alpha);
                *(float2*)(Cf + b8 + c0) = make_float2(a[2] * alpha, a[3] * alpha);
            } else {
                const int cp = pperm(c0);
                __half h0 = __float2half_rn(a[0]), h1 = __float2half_rn(a[1]);
                __half h2 = __float2half_rn(a[2]), h3 = __float2half_rn(a[3]);
                *(__half2*)(Ch + b0 + cp) = __halves2half2(h0, h1);
                *(__half2*)(Ch + b8 + cp) = __halves2half2(h2, h3);
                if (EPI == 1) {
                    *(__half2*)(Cl + b0 + cp) = __halves2half2(
                        __float2half_rn(a[0] - __half2float(h0)),
                        __float2half_rn(a[1] - __half2float(h1)));
                    *(__half2*)(Cl + b8 + cp) = __halves2half2(
                        __float2half_rn(a[2] - __half2float(h2)),
                        __float2half_rn(a[3] - __half2float(h3)));
                }
            }
        }
    }
}

// ---------------- standalone GEMM kernel (Mt partials / logits / out) ----------------
template <int EPI, int PASSES>
__global__ __launch_bounds__(256, 2)
void mma_nt(const __half* __restrict__ Ahi, const __half* __restrict__ Alo,
            const __half* __restrict__ Bhi, const __half* __restrict__ Blo,
            float* __restrict__ Cf, __half* __restrict__ Ch, __half* __restrict__ Cl,
            int K, int lda, int ldb, int ldc,
            long long sA, long long sB, long long sC,
            float alpha, int causal)
{
    extern __shared__ char smc[];
    const int bn = blockIdx.x, bz = blockIdx.z;
    int bm = blockIdx.y;
    if (causal == 1 && bn > bm) return;
    if (causal == 2) bm = gridDim.y - 1 - bm;     // heavy tiles first
    int Keff = K;
    if (causal == 2) { int kl = (bm + 1) * 128; Keff = kl < K ? kl : K; }
    gemm_tile<EPI, PASSES>(Ahi, Alo, Bhi, Blo, Cf, Ch, Cl,
                           K, lda, ldb, ldc, sA, sB, sC, alpha, Keff, bm, bn, bz, smc);
}

// ---------------- fused v + u kernel: one linear grid, tail = cheap v tiles ----------------
// idx < 1024: u tile  (3-pass, EPI=1): u[m,c'] = sum_c x[m,c]*Mt[c',c]
// idx >= 1024: v tile (1-pass, EPI=2): vT[b,h,t] = Wv_h[h,:]*x_h[b,t,:]
__global__ __launch_bounds__(256, 2)
void fused_vu(const __half* __restrict__ xh, const __half* __restrict__ xl,
              const __half* __restrict__ mth, const __half* __restrict__ mtl,
              __half* __restrict__ uh, __half* __restrict__ ul,
              const __half* __restrict__ wvh, __half* __restrict__ vth)
{
    extern __shared__ char smc[];
    const int idx = blockIdx.x;
    if (idx < 1024) {
        const int bm = idx >> 3, bn = idx & 7;     // M=16384/128=128, N=1024/128=8
        gemm_tile<1, 3>(xh, xl, mth, mtl, nullptr, uh, ul,
                        C_, C_, C_, C_, 0, 0, 0, 1.f, C_, bm, bn, 0, smc);
    } else {
        const int j = idx - 1024;
        const int bm = j >> 7;                     // 0..7  (H rows)
        const int bn = (j >> 3) & 15;              // 0..15 (T cols)
        const int bz = j & 7;                      // batch
        gemm_tile<2, 1>(wvh, nullptr, xh, nullptr, nullptr, vth, nullptr,
                        C_, C_, C_, T_, 0, (long long)T_ * C_, (long long)H_ * T_,
                        1.f, C_, bm, bn, bz, smc);
    }
}

// ---------------- elementwise fp16 split, pair-permuted layout ----------------
__global__ void split_kernel(const float* __restrict__ src,
                             __half* __restrict__ hi, __half* __restrict__ lo, int n8)
{
    const int i = blockIdx.x * blockDim.x + threadIdx.x;
    if (i >= n8) return;
    const int u = i & 3;
    const int blk = (i >> 2) * 32;
    uint32_t ho[4], lw[4];
#pragma unroll
    for (int b = 0; b < 4; b++) {
        const float2 v = *(const float2*)(src + blk + 8 * b + 2 * u);
        __half h0 = __float2half_rn(v.x), h1 = __float2half_rn(v.y);
        ho[b] = pack2(h0, h1);
        lw[b] = pack2(__float2half_rn(v.x - __half2float(h0)),
                      __float2half_rn(v.y - __half2float(h1)));
    }
    ((uint2*)(hi + blk))[u * 2 + 0] = make_uint2(ho[0], ho[1]);
    ((uint2*)(hi + blk))[u * 2 + 1] = make_uint2(ho[2], ho[3]);
    if (lo) {
        ((uint2*)(lo + blk))[u * 2 + 0] = make_uint2(lw[0], lw[1]);
        ((uint2*)(lo + blk))[u * 2 + 1] = make_uint2(lw[2], lw[3]);
    }
}

// ---------------- Mt split-K reduce + permuted fp16 hi/lo split ----------------
__global__ void mt_reduce_split(const float* __restrict__ p,
                                __half* __restrict__ hi, __half* __restrict__ lo, int n8)
{
    const int i = blockIdx.x * blockDim.x + threadIdx.x;
    if (i >= n8) return;
    const size_t CC = (size_t)C_ * C_;
    const int u = i & 3;
    const int blk = (i >> 2) * 32;
    uint32_t ho[4], lw[4];
#pragma unroll
    for (int b = 0; b < 4; b++) {
        const size_t o = (size_t)blk + 8 * b + 2 * u;
        float2 v0 = *(const float2*)(p + o);
        float2 v1 = *(const float2*)(p + CC + o);
        float2 v2 = *(const float2*)(p + 2 * CC + o);
        float2 v3 = *(const float2*)(p + 3 * CC + o);
        float x = (v0.x + v1.x) + (v2.x + v3.x);
        float y = (v0.y + v1.y) + (v2.y + v3.y);
        __half h0 = __float2half_rn(x), h1 = __float2half_rn(y);
        ho[b] = pack2(h0, h1);
        lw[b] = pack2(__float2half_rn(x - __half2float(h0)),
                      __float2half_rn(y - __half2float(h1)));
    }
    ((uint2*)(hi + blk))[u * 2 + 0] = make_uint2(ho[0], ho[1]);
    ((uint2*)(hi + blk))[u * 2 + 1] = make_uint2(ho[2], ho[3]);
    ((uint2*)(lo + blk))[u * 2 + 0] = make_uint2(lw[0], lw[1]);
    ((uint2*)(lo + blk))[u * 2 + 1] = make_uint2(lw[2], lw[3]);
}

// ---------------- transpose + fp16 split: W[H,C] -> Wt hi/lo [C,H], permuted along H ----------------
__global__ __launch_bounds__(256)
void transpose_split_kernel(const float* __restrict__ W,
                            __half* __restrict__ th, __half* __restrict__ tl,
                            int Hd, int Cd)
{
    __shared__ float tile[64][33];
    const int c0 = blockIdx.x * 32, h0 = blockIdx.y * 64;
    const int tid = threadIdx.x;
    {
        const int lc = tid & 31;
        const int lh = tid >> 5;
#pragma unroll
        for (int i = 0; i < 8; i++)
            tile[lh + 8 * i][lc] = W[(size_t)(h0 + lh + 8 * i) * Cd + c0 + lc];
    }
    __syncthreads();
    const int lc = tid >> 3;
    const int lp = tid & 7;
#pragma unroll
    for (int i = 0; i < 4; i++) {
        const int p = lp + 8 * i;
        const int b = p >> 4;
        const int pin = p & 15;
        const int ppin = ((pin & 3) << 2) | (pin >> 2);
        const int hs = p * 2;
        const float v0 = tile[hs][lc], v1 = tile[hs + 1][lc];
        const __half h0_ = __float2half_rn(v0), h1_ = __float2half_rn(v1);
        const size_t o = (size_t)(c0 + lc) * Hd + h0 + b * 32 + ppin * 2;
        *(__half2*)(th + o) = __halves2half2(h0_, h1_);
        *(__half2*)(tl + o) = __halves2half2(__float2half_rn(v0 - __half2float(h0_)),
                                             __float2half_rn(v1 - __half2float(h1_)));
    }
}

// ---------------- single-sweep causal softmax + fp16 hi write (permuted cols) ----------------
__global__ __launch_bounds__(256)
void softmax_split_kernel(float* __restrict__ W, __half* __restrict__ Wh, int T)
{
    const long long row = blockIdx.x;
    const int t = (int)(row % T);
    float* p   = W  + row * (long long)T;
    __half* ph = Wh + row * (long long)T;
    const int n = t + 1;
    const int tid = threadIdx.x;
    const int base = tid * 8;

    __shared__ float red[8];

    float v[8];
    {
        float4 a = *(const float4*)(p + base);
        float4 b = *(const float4*)(p + base + 4);
        v[0] = a.x; v[1] = a.y; v[2] = a.z; v[3] = a.w;
        v[4] = b.x; v[5] = b.y; v[6] = b.z; v[7] = b.w;
    }
#pragma unroll
    for (int j = 0; j < 8; j++)
        if (base + j >= n) v[j] = -3.4e38f;

    float m = v[0];
#pragma unroll
    for (int j = 1; j < 8; j++) m = fmaxf(m, v[j]);
#pragma unroll
    for (int o = 16; o; o >>= 1) m = fmaxf(m, __shfl_xor_sync(0xffffffffu, m, o));
    if ((tid & 31) == 0) red[tid >> 5] = m;
    __syncthreads();
    if (tid < 32) {
        float mb = (tid < 8) ? red[tid] : -3.4e38f;
#pragma unroll
        for (int o = 4; o; o >>= 1) mb = fmaxf(mb, __shfl_xor_sync(0xffffffffu, mb, o));
        if (tid == 0) red[0] = mb;
    }
    __syncthreads();
    m = red[0];
    __syncthreads();

    float s = 0.f;
#pragma unroll
    for (int j = 0; j < 8; j++) {
        v[j] = (base + j < n) ? expf(v[j] - m) : 0.f;
        s += v[j];
    }
#pragma unroll
    for (int o = 16; o; o >>= 1) s += __shfl_xor_sync(0xffffffffu, s, o);
    if ((tid & 31) == 0) red[tid >> 5] = s;
    __syncthreads();
    if (tid < 32) {
        float sb = (tid < 8) ? red[tid] : 0.f;
#pragma unroll
        for (int o = 4; o; o >>= 1) sb += __shfl_xor_sync(0xffffffffu, sb, o);
        if (tid == 0) red[0] = sb;
    }
    __syncthreads();
    const float inv = 1.f / red[0];

#pragma unroll
    for (int j = 0; j < 8; j++) v[j] *= inv;
    *(float4*)(p + base)     = make_float4(v[0], v[1], v[2], v[3]);
    *(float4*)(p + base + 4) = make_float4(v[4], v[5], v[6], v[7]);

    const int u = tid & 3;
    __half* phb = ph + (base & ~31);
#pragma unroll
    for (int b = 0; b < 4; b++) {
        *(__half2*)(phb + (b * 4 + u) * 2) =
            __halves2half2(__float2half_rn(v[2 * b]), __float2half_rn(v[2 * b + 1]));
    }
}

// ---------------- launch ----------------
extern "C" void kernel_launch(void* const* d_in, const int* in_sizes, int n_in,
                              void* d_out, int out_size)
{
    (void)in_sizes; (void)n_in; (void)out_size;
    const float* x  = (const float*)d_in[0];
    const float* Wk = (const float*)d_in[1];
    const float* Wq = (const float*)d_in[2];
    const float* Wv = (const float*)d_in[3];

    float* out = (float*)d_out;                      // [B, T, H]
    float* wei = out + (size_t)B_ * T_ * H_;         // [B, T, T]

    __half *xh, *xl, *wqth, *wqtl, *wkth, *wktl, *mth, *mtl, *uh, *ul, *wvh, *vth, *weih;
    float* mtp;
    cudaGetSymbolAddress((void**)&xh, g_xh);     cudaGetSymbolAddress((void**)&xl, g_xl);
    cudaGetSymbolAddress((void**)&wqth, g_wqth); cudaGetSymbolAddress((void**)&wqtl, g_wqtl);
    cudaGetSymbolAddress((void**)&wkth, g_wkth); cudaGetSymbolAddress((void**)&wktl, g_wktl);
    cudaGetSymbolAddress((void**)&mtp, g_mtp);
    cudaGetSymbolAddress((void**)&mth, g_mth);   cudaGetSymbolAddress((void**)&mtl, g_mtl);
    cudaGetSymbolAddress((void**)&uh, g_uh);     cudaGetSymbolAddress((void**)&ul, g_ul);
    cudaGetSymbolAddress((void**)&wvh, g_wvh);
    cudaGetSymbolAddress((void**)&vth, g_vth);
    cudaGetSymbolAddress((void**)&weih, g_weih);

    cudaFuncSetAttribute(mma_nt<0,3>, cudaFuncAttributeMaxDynamicSharedMemorySize, GEMM_SMEM);
    cudaFuncSetAttribute(mma_nt<0,1>, cudaFuncAttributeMaxDynamicSharedMemorySize, GEMM_SMEM);
    cudaFuncSetAttribute(fused_vu,    cudaFuncAttributeMaxDynamicSharedMemorySize, GEMM_SMEM);

    const dim3 blk(256);

    // 1) splits: x -> hi/lo; Wv -> hi; Wq/Wk -> transposed hi/lo (permuted along H)
    {
        const int n8x = (B_ * T_ * C_) / 8;
        split_kernel<<<(n8x + 255) / 256, 256>>>(x, xh, xl, n8x);
        const int n8w = (H_ * C_) / 8;
        split_kernel<<<(n8w + 255) / 256, 256>>>(Wv, wvh, nullptr, n8w);
        const dim3 gt(C_ / 32, H_ / 64);
        transpose_split_kernel<<<gt, blk>>>(Wq, wqth, wqtl, H_, C_);
        transpose_split_kernel<<<gt, blk>>>(Wk, wkth, wktl, H_, C_);
    }

    // 2) Mt partials via split-K=4, then reduce + permuted fp16 hi/lo split.
    {
        const dim3 g(C_ / 128, C_ / 128, 4);
        mma_nt<0,3><<<g, blk, GEMM_SMEM>>>(wkth, wktl, wqth, wqtl, mtp, nullptr, nullptr,
                                           256, H_, H_, C_,
                                           256, 256, (long long)C_ * C_, 1.f, 0);
        mt_reduce_split<<<(C_ * C_ / 8 + 255) / 256, 256>>>(mtp, mth, mtl, C_ * C_ / 8);
    }

    // 3+4) fused: u (3-pass, tiles 0..1023) + v (1-pass, tiles 1024..2047)
    fused_vu<<<2048, blk, GEMM_SMEM>>>(xh, xl, mth, mtl, uh, ul, wvh, vth);

    // 5) logits: wei[b,t,s] = (1/32) sum_c' u·x, 3-pass, causal block skip
    {
        const dim3 g(T_ / 128, T_ / 128, B_);
        mma_nt<0,3><<<g, blk, GEMM_SMEM>>>(uh, ul, xh, xl, wei, nullptr, nullptr,
                                           C_, C_, C_, T_,
                                           (long long)T_ * C_, (long long)T_ * C_,
                                           (long long)T_ * T_, 0.03125f, 1);
    }

    // 6) single-sweep causal softmax + permuted fp16 hi of wei
    softmax_split_kernel<<<B_ * T_, 256>>>(wei, weih, T_);

    // 7) out = wei_h · vT_h, 1-pass, causal K, heavy-first
    {
        const dim3 g(H_ / 128, T_ / 128, B_);
        mma_nt<0,1><<<g, blk, GEMM_SMEM>>>(weih, nullptr, vth, nullptr, out, nullptr, nullptr,
                                           T_, T_, T_, H_,
                                           (long long)T_ * T_, (long long)H_ * T_,
                                           (long long)T_ * H_, 1.f, 2);
    }
}

// round 14
// speedup vs baseline: 1.2649x; 1.0249x over previous
#include <cuda_runtime.h>
#include <cuda_fp16.h>
#include <cstdint>

// ---------------- problem shape ----------------
static constexpr int B_ = 8;
static constexpr int T_ = 2048;
static constexpr int C_ = 1024;
static constexpr int H_ = 1024;

// ---------------- scratch (__device__ globals) ----------------
// fp16 hi/lo arrays, PAIR-PERMUTED along the contraction dim (4x4 pair
// transpose within each 32-elem K-block; involution; applied to both operands).
__device__ __half g_xh[(size_t)B_ * T_ * C_];
__device__ __half g_xl[(size_t)B_ * T_ * C_];
__device__ __half g_wqth[(size_t)C_ * H_];   // Wq^T [C,H], permuted along H
__device__ __half g_wqtl[(size_t)C_ * H_];
__device__ __half g_wkth[(size_t)C_ * H_];
__device__ __half g_wktl[(size_t)C_ * H_];
__device__ float  g_mtp[(size_t)4 * C_ * C_];  // Mt split-K partials (fp32)
__device__ __half g_mth[(size_t)C_ * C_];      // Mt hi/lo, permuted along c
__device__ __half g_mtl[(size_t)C_ * C_];
__device__ __half g_uh[(size_t)B_ * T_ * C_];  // u = x·M, permuted along c'
__device__ __half g_ul[(size_t)B_ * T_ * C_];
__device__ __half g_wvh[(size_t)H_ * C_];
__device__ __half g_vth[(size_t)B_ * H_ * T_];   // v^T [b][h][t], hi only
__device__ __half g_weih[(size_t)B_ * T_ * T_];  // wei fp16 hi only

// ---------------- helpers ----------------
__device__ __forceinline__ uint32_t pack2(__half a, __half b) {
    __half2 h2 = __halves2half2(a, b);
    return *reinterpret_cast<uint32_t*>(&h2);
}
__device__ __forceinline__ void cpa16(uint32_t dst, const void* src) {
    asm volatile("cp.async.cg.shared.global [%0], [%1], 16;" :: "r"(dst), "l"(src));
}
__device__ __forceinline__ void cp_commit() {
    asm volatile("cp.async.commit_group;" ::: "memory");
}
template <int N>
__device__ __forceinline__ void cp_wait() {
    asm volatile("cp.async.wait_group %0;" :: "n"(N) : "memory");
}
__device__ __forceinline__ uint32_t smem_u32(const void* p) {
    uint32_t a;
    asm("{ .reg .u64 t; cvta.to.shared.u64 t, %1; cvt.u32.u64 %0, t; }" : "=r"(a) : "l"(p));
    return a;
}
// D += A*B, m16n8k16 fp16 inputs, fp32 accum
__device__ __forceinline__ void mma16(float* d, uint32_t a0, uint32_t a1, uint32_t a2,
                                      uint32_t a3, uint32_t b0, uint32_t b1) {
    asm volatile(
        "mma.sync.aligned.m16n8k16.row.col.f32.f16.f16.f32 "
        "{%0,%1,%2,%3},{%4,%5,%6,%7},{%8,%9},{%0,%1,%2,%3};"
        : "+f"(d[0]), "+f"(d[1]), "+f"(d[2]), "+f"(d[3])
        : "r"(a0), "r"(a1), "r"(a2), "r"(a3), "r"(b0), "r"(b1));
}
// permuted element index within 32-block (pair-level 4x4 transpose; involution)
__device__ __forceinline__ int pperm(int c) {
    const int p = (c & 31) >> 1;
    const int pp = ((p & 3) << 2) | (p >> 2);
    return (c & ~31) | (pp << 1) | (c & 1);
}

// ---------------- FP16 multi-pass NT GEMM via mma.sync (pair-permuted operands) ----------------
// C[m,n] = alpha * sum_k A[m,k]*B[n,k]. CTA 128x128, BK=32, 256 thr (2x4 warps).
// PASSES=3: AhBh + AlBh + AhBl.  PASSES=1: AhBh only.
// EPI=0: Cf = fp32*alpha (linear cols). EPI=1: Ch/Cl fp16 hi/lo (permuted cols).
// EPI=2: Ch fp16 hi only (permuted cols).
// causal: 0 none; 1 skip block if bn>bm; 2 Keff=min(K,(bm+1)*128), heavy-first bm remap.
static constexpr int GEMM_SMEM = 2 * 32768;   // 64 KB double buffer

template <int EPI, int PASSES>
__global__ __launch_bounds__(256, 2)
void mma_nt(const __half* __restrict__ Ahi, const __half* __restrict__ Alo,
            const __half* __restrict__ Bhi, const __half* __restrict__ Blo,
            float* __restrict__ Cf, __half* __restrict__ Ch, __half* __restrict__ Cl,
            int K, int lda, int ldb, int ldc,
            long long sA, long long sB, long long sC,
            float alpha, int causal)
{
    extern __shared__ char smc[];
    const int bn = blockIdx.x, bz = blockIdx.z;
    int bm = blockIdx.y;
    if (causal == 1 && bn > bm) return;
    if (causal == 2) bm = gridDim.y - 1 - bm;     // heavy tiles first
    int Keff = K;
    if (causal == 2) { int kl = (bm + 1) * 128; Keff = kl < K ? kl : K; }
    const int nk = Keff / 32;

    const __half* Ah = Ahi + (size_t)bz * sA;
    const __half* Al = (PASSES >= 2) ? Alo + (size_t)bz * sA : nullptr;
    const __half* Bh = Bhi + (size_t)bz * sB;
    const __half* Bl = (PASSES == 3) ? Blo + (size_t)bz * sB : nullptr;

    const int tid = threadIdx.x;
    const int lane = tid & 31, w = tid >> 5;
    const int wm = w & 1, wn = w >> 1;            // 2 (M) x 4 (N) warp grid
    const int gr = lane >> 2, tc = lane & 3;
    const uint32_t sbase = smem_u32(smc);

    // stage loader: arrays of [128][32] halves (64B rows); 512 16B-chunks each.
    auto load_stage = [&](int kt, int s) {
        const int k0 = kt * 32;
        const uint32_t dst = sbase + (uint32_t)s * 32768u;
#pragma unroll
        for (int t = 0; t < 2; t++) {
            const int idx = t * 256 + tid;         // 0..511
            const int row = idx >> 2, j = (idx & 3) * 8;
            const uint32_t off = (uint32_t)(row * 64 + j * 2);
            const size_t ga = (size_t)(bm * 128 + row) * lda + k0 + j;
            const size_t gb = (size_t)(bn * 128 + row) * ldb + k0 + j;
            cpa16(dst + off,           Ah + ga);
            if (PASSES >= 2) cpa16(dst + 8192u + off, Al + ga);
            cpa16(dst + 16384u + off,  Bh + gb);
            if (PASSES == 3) cpa16(dst + 24576u + off, Bl + gb);
        }
        cp_commit();
    };

    float acc[4][4][4];
#pragma unroll
    for (int i = 0; i < 4; i++)
#pragma unroll
        for (int j = 0; j < 4; j++)
#pragma unroll
            for (int r = 0; r < 4; r++) acc[i][j][r] = 0.f;

    load_stage(0, 0);

    const int rbA = (wm * 64 + gr) * 4 + tc;       // uint4 index of A frag row
    const int rbB = (wn * 32 + gr) * 4 + tc;

    for (int kt = 0; kt < nk; kt++) {
        const int s = kt & 1;
        cp_wait<0>();
        __syncthreads();                            // data(kt) visible; compute(kt-1) done
        if (kt + 1 < nk) load_stage(kt + 1, s ^ 1); // overlaps compute(kt)

        const uint4* S   = (const uint4*)(smc + s * 32768);
        const uint4* pAh = S;
        const uint4* pAl = S + 512;
        const uint4* pBh = S + 1024;
        const uint4* pBl = S + 1536;

        uint4 bh0 = pBh[rbB], bh1 = pBh[rbB + 32], bh2 = pBh[rbB + 64], bh3 = pBh[rbB + 96];

#pragma unroll
        for (int fm = 0; fm < 4; fm++) {
            const int ra = rbA + fm * 64;
            uint4 a0 = pAh[ra], a8 = pAh[ra + 32];
            uint4 l0, l8;
            if (PASSES >= 2) { l0 = pAl[ra]; l8 = pAl[ra + 32]; }
#pragma unroll
            for (int fn = 0; fn < 4; fn++) {
                const uint4 bh = fn == 0 ? bh0 : fn == 1 ? bh1 : fn == 2 ? bh2 : bh3;
                float* a = acc[fm][fn];
                mma16(a, a0.x, a8.x, a0.y, a8.y, bh.x, bh.y);
                if (PASSES >= 2) mma16(a, l0.x, l8.x, l0.y, l8.y, bh.x, bh.y);
                mma16(a, a0.z, a8.z, a0.w, a8.w, bh.z, bh.w);
                if (PASSES >= 2) mma16(a, l0.z, l8.z, l0.w, l8.w, bh.z, bh.w);
            }
        }

        if (PASSES == 3) {
            uint4 bl0 = pBl[rbB], bl1 = pBl[rbB + 32], bl2 = pBl[rbB + 64], bl3 = pBl[rbB + 96];
#pragma unroll
            for (int fm = 0; fm < 4; fm++) {
                const int ra = rbA + fm * 64;
                uint4 a0 = pAh[ra], a8 = pAh[ra + 32];
#pragma unroll
                for (int fn = 0; fn < 4; fn++) {
                    const uint4 bl = fn == 0 ? bl0 : fn == 1 ? bl1 : fn == 2 ? bl2 : bl3;
                    float* a = acc[fm][fn];
                    mma16(a, a0.x, a8.x, a0.y, a8.y, bl.x, bl.y);
                    mma16(a, a0.z, a8.z, a0.w, a8.w, bl.z, bl.w);
                }
            }
        }
    }

    // ---- epilogue ----
#pragma unroll
    for (int fm = 0; fm < 4; fm++) {
        const int r0 = bm * 128 + wm * 64 + fm * 16 + gr;
#pragma unroll
        for (int fn = 0; fn < 4; fn++) {
            const int c0 = bn * 128 + wn * 32 + fn * 8 + 2 * tc;
            const size_t b0 = (size_t)bz * sC + (size_t)r0 * ldc;
            const size_t b8 = b0 + (size_t)8 * ldc;
            const float* a = acc[fm][fn];
            if (EPI == 0) {
                *(float2*)(Cf + b0 + c0) = make_float2(a[0] * alpha, a[1] * alpha);
                *(float2*)(Cf + b8 + c0) = make_float2(a[2] * alpha, a[3] * alpha);
            } else {
                const int cp = pperm(c0);
                __half h0 = __float2half_rn(a[0]), h1 = __float2half_rn(a[1]);
                __half h2 = __float2half_rn(a[2]), h3 = __float2half_rn(a[3]);
                *(__half2*)(Ch + b0 + cp) = __halves2half2(h0, h1);
                *(__half2*)(Ch + b8 + cp) = __halves2half2(h2, h3);
                if (EPI == 1) {
                    *(__half2*)(Cl + b0 + cp) = __halves2half2(
                        __float2half_rn(a[0] - __half2float(h0)),
                        __float2half_rn(a[1] - __half2float(h1)));
                    *(__half2*)(Cl + b8 + cp) = __halves2half2(
                        __float2half_rn(a[2] - __half2float(h2)),
                        __float2half_rn(a[3] - __half2float(h3)));
                }
            }
        }
    }
}

// ---------------- elementwise fp16 split, pair-permuted layout ----------------
__global__ void split_kernel(const float* __restrict__ src,
                             __half* __restrict__ hi, __half* __restrict__ lo, int n8)
{
    const int i = blockIdx.x * blockDim.x + threadIdx.x;
    if (i >= n8) return;
    const int u = i & 3;
    const int blk = (i >> 2) * 32;
    uint32_t ho[4], lw[4];
#pragma unroll
    for (int b = 0; b < 4; b++) {
        const float2 v = *(const float2*)(src + blk + 8 * b + 2 * u);
        __half h0 = __float2half_rn(v.x), h1 = __float2half_rn(v.y);
        ho[b] = pack2(h0, h1);
        lw[b] = pack2(__float2half_rn(v.x - __half2float(h0)),
                      __float2half_rn(v.y - __half2float(h1)));
    }
    ((uint2*)(hi + blk))[u * 2 + 0] = make_uint2(ho[0], ho[1]);
    ((uint2*)(hi + blk))[u * 2 + 1] = make_uint2(ho[2], ho[3]);
    if (lo) {
        ((uint2*)(lo + blk))[u * 2 + 0] = make_uint2(lw[0], lw[1]);
        ((uint2*)(lo + blk))[u * 2 + 1] = make_uint2(lw[2], lw[3]);
    }
}

// ---------------- Mt split-K reduce + permuted fp16 hi/lo split ----------------
__global__ void mt_reduce_split(const float* __restrict__ p,
                                __half* __restrict__ hi, __half* __restrict__ lo, int n8)
{
    const int i = blockIdx.x * blockDim.x + threadIdx.x;
    if (i >= n8) return;
    const size_t CC = (size_t)C_ * C_;
    const int u = i & 3;
    const int blk = (i >> 2) * 32;
    uint32_t ho[4], lw[4];
#pragma unroll
    for (int b = 0; b < 4; b++) {
        const size_t o = (size_t)blk + 8 * b + 2 * u;
        float2 v0 = *(const float2*)(p + o);
        float2 v1 = *(const float2*)(p + CC + o);
        float2 v2 = *(const float2*)(p + 2 * CC + o);
        float2 v3 = *(const float2*)(p + 3 * CC + o);
        float x = (v0.x + v1.x) + (v2.x + v3.x);
        float y = (v0.y + v1.y) + (v2.y + v3.y);
        __half h0 = __float2half_rn(x), h1 = __float2half_rn(y);
        ho[b] = pack2(h0, h1);
        lw[b] = pack2(__float2half_rn(x - __half2float(h0)),
                      __float2half_rn(y - __half2float(h1)));
    }
    ((uint2*)(hi + blk))[u * 2 + 0] = make_uint2(ho[0], ho[1]);
    ((uint2*)(hi + blk))[u * 2 + 1] = make_uint2(ho[2], ho[3]);
    ((uint2*)(lo + blk))[u * 2 + 0] = make_uint2(lw[0], lw[1]);
    ((uint2*)(lo + blk))[u * 2 + 1] = make_uint2(lw[2], lw[3]);
}

// ---------------- fused dual transpose + fp16 split: W[H,C] -> Wt hi/lo [C,H] ----------------
// blockIdx.z selects (W0 -> t0) or (W1 -> t1). Permuted along H.
__global__ __launch_bounds__(256)
void transpose_split2_kernel(const float* __restrict__ W0,
                             __half* __restrict__ t0h, __half* __restrict__ t0l,
                             const float* __restrict__ W1,
                             __half* __restrict__ t1h, __half* __restrict__ t1l,
                             int Hd, int Cd)
{
    const float* W = (blockIdx.z == 0) ? W0 : W1;
    __half* th = (blockIdx.z == 0) ? t0h : t1h;
    __half* tl = (blockIdx.z == 0) ? t0l : t1l;

    __shared__ float tile[64][33];
    const int c0 = blockIdx.x * 32, h0 = blockIdx.y * 64;
    const int tid = threadIdx.x;
    {
        const int lc = tid & 31;
        const int lh = tid >> 5;
#pragma unroll
        for (int i = 0; i < 8; i++)
            tile[lh + 8 * i][lc] = W[(size_t)(h0 + lh + 8 * i) * Cd + c0 + lc];
    }
    __syncthreads();
    const int lc = tid >> 3;
    const int lp = tid & 7;
#pragma unroll
    for (int i = 0; i < 4; i++) {
        const int p = lp + 8 * i;
        const int b = p >> 4;
        const int pin = p & 15;
        const int ppin = ((pin & 3) << 2) | (pin >> 2);
        const int hs = p * 2;
        const float v0 = tile[hs][lc], v1 = tile[hs + 1][lc];
        const __half h0_ = __float2half_rn(v0), h1_ = __float2half_rn(v1);
        const size_t o = (size_t)(c0 + lc) * Hd + h0 + b * 32 + ppin * 2;
        *(__half2*)(th + o) = __halves2half2(h0_, h1_);
        *(__half2*)(tl + o) = __halves2half2(__float2half_rn(v0 - __half2float(h0_)),
                                             __float2half_rn(v1 - __half2float(h1_)));
    }
}

// ---------------- single-sweep causal softmax + fp16 hi write (permuted cols) ----------------
// Prefix-predicated loads: only the causal prefix is read from gmem.
__global__ __launch_bounds__(256)
void softmax_split_kernel(float* __restrict__ W, __half* __restrict__ Wh, int T)
{
    const long long row = blockIdx.x;
    const int t = (int)(row % T);
    float* p   = W  + row * (long long)T;
    __half* ph = Wh + row * (long long)T;
    const int n = t + 1;
    const int tid = threadIdx.x;
    const int base = tid * 8;

    __shared__ float red[8];

    float v[8];
    if (base + 7 < n) {                               // fully inside prefix: vector loads
        float4 a = *(const float4*)(p + base);
        float4 b = *(const float4*)(p + base + 4);
        v[0] = a.x; v[1] = a.y; v[2] = a.z; v[3] = a.w;
        v[4] = b.x; v[5] = b.y; v[6] = b.z; v[7] = b.w;
    } else {                                          // boundary / outside: guarded scalars
#pragma unroll
        for (int j = 0; j < 8; j++)
            v[j] = (base + j < n) ? p[base + j] : -3.4e38f;
    }

    float m = v[0];
#pragma unroll
    for (int j = 1; j < 8; j++) m = fmaxf(m, v[j]);
#pragma unroll
    for (int o = 16; o; o >>= 1) m = fmaxf(m, __shfl_xor_sync(0xffffffffu, m, o));
    if ((tid & 31) == 0) red[tid >> 5] = m;
    __syncthreads();
    if (tid < 32) {
        float mb = (tid < 8) ? red[tid] : -3.4e38f;
#pragma unroll
        for (int o = 4; o; o >>= 1) mb = fmaxf(mb, __shfl_xor_sync(0xffffffffu, mb, o));
        if (tid == 0) red[0] = mb;
    }
    __syncthreads();
    m = red[0];
    __syncthreads();

    float s = 0.f;
#pragma unroll
    for (int j = 0; j < 8; j++) {
        v[j] = (base + j < n) ? __expf(v[j] - m) : 0.f;
        s += v[j];
    }
#pragma unroll
    for (int o = 16; o; o >>= 1) s += __shfl_xor_sync(0xffffffffu, s, o);
    if ((tid & 31) == 0) red[tid >> 5] = s;
    __syncthreads();
    if (tid < 32) {
        float sb = (tid < 8) ? red[tid] : 0.f;
#pragma unroll
        for (int o = 4; o; o >>= 1) sb += __shfl_xor_sync(0xffffffffu, sb, o);
        if (tid == 0) red[0] = sb;
    }
    __syncthreads();
    const float inv = 1.f / red[0];

#pragma unroll
    for (int j = 0; j < 8; j++) v[j] *= inv;
    *(float4*)(p + base)     = make_float4(v[0], v[1], v[2], v[3]);
    *(float4*)(p + base + 4) = make_float4(v[4], v[5], v[6], v[7]);

    const int u = tid & 3;
    __half* phb = ph + (base & ~31);
#pragma unroll
    for (int b = 0; b < 4; b++) {
        *(__half2*)(phb + (b * 4 + u) * 2) =
            __halves2half2(__float2half_rn(v[2 * b]), __float2half_rn(v[2 * b + 1]));
    }
}

// ---------------- launch ----------------
extern "C" void kernel_launch(void* const* d_in, const int* in_sizes, int n_in,
                              void* d_out, int out_size)
{
    (void)in_sizes; (void)n_in; (void)out_size;
    const float* x  = (const float*)d_in[0];
    const float* Wk = (const float*)d_in[1];
    const float* Wq = (const float*)d_in[2];
    const float* Wv = (const float*)d_in[3];

    float* out = (float*)d_out;                      // [B, T, H]
    float* wei = out + (size_t)B_ * T_ * H_;         // [B, T, T]

    __half *xh, *xl, *wqth, *wqtl, *wkth, *wktl, *mth, *mtl, *uh, *ul, *wvh, *vth, *weih;
    float* mtp;
    cudaGetSymbolAddress((void**)&xh, g_xh);     cudaGetSymbolAddress((void**)&xl, g_xl);
    cudaGetSymbolAddress((void**)&wqth, g_wqth); cudaGetSymbolAddress((void**)&wqtl, g_wqtl);
    cudaGetSymbolAddress((void**)&wkth, g_wkth); cudaGetSymbolAddress((void**)&wktl, g_wktl);
    cudaGetSymbolAddress((void**)&mtp, g_mtp);
    cudaGetSymbolAddress((void**)&mth, g_mth);   cudaGetSymbolAddress((void**)&mtl, g_mtl);
    cudaGetSymbolAddress((void**)&uh, g_uh);     cudaGetSymbolAddress((void**)&ul, g_ul);
    cudaGetSymbolAddress((void**)&wvh, g_wvh);
    cudaGetSymbolAddress((void**)&vth, g_vth);
    cudaGetSymbolAddress((void**)&weih, g_weih);

    cudaFuncSetAttribute(mma_nt<0,3>, cudaFuncAttributeMaxDynamicSharedMemorySize, GEMM_SMEM);
    cudaFuncSetAttribute(mma_nt<1,3>, cudaFuncAttributeMaxDynamicSharedMemorySize, GEMM_SMEM);
    cudaFuncSetAttribute(mma_nt<2,1>, cudaFuncAttributeMaxDynamicSharedMemorySize, GEMM_SMEM);
    cudaFuncSetAttribute(mma_nt<0,1>, cudaFuncAttributeMaxDynamicSharedMemorySize, GEMM_SMEM);

    const dim3 blk(256);

    // 1) splits: x -> hi/lo; Wv -> hi; Wq & Wk -> transposed hi/lo in one launch
    {
        const int n8x = (B_ * T_ * C_) / 8;
        split_kernel<<<(n8x + 255) / 256, 256>>>(x, xh, xl, n8x);
        const int n8w = (H_ * C_) / 8;
        split_kernel<<<(n8w + 255) / 256, 256>>>(Wv, wvh, nullptr, n8w);
        const dim3 gt(C_ / 32, H_ / 64, 2);
        transpose_split2_kernel<<<gt, blk>>>(Wq, wqth, wqtl, Wk, wkth, wktl, H_, C_);
    }

    // 2) Mt partials via split-K=4, then reduce + permuted fp16 hi/lo split.
    {
        const dim3 g(C_ / 128, C_ / 128, 4);
        mma_nt<0,3><<<g, blk, GEMM_SMEM>>>(wkth, wktl, wqth, wqtl, mtp, nullptr, nullptr,
                                           256, H_, H_, C_,
                                           256, 256, (long long)C_ * C_, 1.f, 0);
        mt_reduce_split<<<(C_ * C_ / 8 + 255) / 256, 256>>>(mtp, mth, mtl, C_ * C_ / 8);
    }

    // 3) v: vT[b,h,t] = Wv_h[h,:]·x_h[b,t,:], 1-pass, hi-only
    {
        const dim3 g(T_ / 128, H_ / 128, B_);
        mma_nt<2,1><<<g, blk, GEMM_SMEM>>>(wvh, nullptr, xh, nullptr, nullptr, vth, nullptr,
                                           C_, C_, C_, T_,
                                           0, (long long)T_ * C_, (long long)H_ * T_, 1.f, 0);
    }

    // 4) u[m,c'] = sum_c x[m,c]·Mt[c',c], 3-pass, hi/lo out
    {
        const dim3 g(C_ / 128, (B_ * T_) / 128, 1);
        mma_nt<1,3><<<g, blk, GEMM_SMEM>>>(xh, xl, mth, mtl, nullptr, uh, ul,
                                           C_, C_, C_, C_, 0, 0, 0, 1.f, 0);
    }

    // 5) logits: wei[b,t,s] = (1/32) sum_c' u·x, 3-pass, causal block skip
    {
        const dim3 g(T_ / 128, T_ / 128, B_);
        mma_nt<0,3><<<g, blk, GEMM_SMEM>>>(uh, ul, xh, xl, wei, nullptr, nullptr,
                                           C_, C_, C_, T_,
                                           (long long)T_ * C_, (long long)T_ * C_,
                                           (long long)T_ * T_, 0.03125f, 1);
    }

    // 6) single-sweep causal softmax (prefix reads) + permuted fp16 hi of wei
    softmax_split_kernel<<<B_ * T_, 256>>>(wei, weih, T_);

    // 7) out = wei_h · vT_h, 1-pass, causal K, heavy-first
    {
        const dim3 g(H_ / 128, T_ / 128, B_);
        mma_nt<0,1><<<g, blk, GEMM_SMEM>>>(weih, nullptr, vth, nullptr, out, nullptr, nullptr,
                                           T_, T_, T_, H_,
                                           (long long)T_ * T_, (long long)H_ * T_,
                                           (long long)T_ * H_, 1.f, 2);
    }
}

// round 15
// speedup vs baseline: 1.2765x; 1.0092x over previous
#include <cuda_runtime.h>
#include <cuda_fp16.h>
#include <cstdint>

// ---------------- problem shape ----------------
static constexpr int B_ = 8;
static constexpr int T_ = 2048;
static constexpr int C_ = 1024;
static constexpr int H_ = 1024;

// ---------------- scratch (__device__ globals) ----------------
// fp16 hi/lo arrays, PAIR-PERMUTED along the contraction dim (4x4 pair
// transpose within each 32-elem K-block; involution; applied to both operands).
__device__ __half g_xh[(size_t)B_ * T_ * C_];
__device__ __half g_xl[(size_t)B_ * T_ * C_];
__device__ __half g_wqth[(size_t)C_ * H_];   // Wq^T [C,H], permuted along H
__device__ __half g_wqtl[(size_t)C_ * H_];
__device__ __half g_wkth[(size_t)C_ * H_];
__device__ __half g_wktl[(size_t)C_ * H_];
__device__ float  g_mtp[(size_t)4 * C_ * C_];  // Mt split-K partials (fp32)
__device__ __half g_mth[(size_t)C_ * C_];      // Mt hi/lo, permuted along c
__device__ __half g_mtl[(size_t)C_ * C_];
__device__ __half g_uh[(size_t)B_ * T_ * C_];  // u = x·M, permuted along c'
__device__ __half g_ul[(size_t)B_ * T_ * C_];
__device__ __half g_wvh[(size_t)H_ * C_];
__device__ __half g_vth[(size_t)B_ * H_ * T_];   // v^T [b][h][t], hi only
__device__ __half g_weih[(size_t)B_ * T_ * T_];  // wei fp16 hi only

// ---------------- helpers ----------------
__device__ __forceinline__ uint32_t pack2(__half a, __half b) {
    __half2 h2 = __halves2half2(a, b);
    return *reinterpret_cast<uint32_t*>(&h2);
}
__device__ __forceinline__ void cpa16(uint32_t dst, const void* src) {
    asm volatile("cp.async.cg.shared.global [%0], [%1], 16;" :: "r"(dst), "l"(src));
}
__device__ __forceinline__ void cp_commit() {
    asm volatile("cp.async.commit_group;" ::: "memory");
}
template <int N>
__device__ __forceinline__ void cp_wait() {
    asm volatile("cp.async.wait_group %0;" :: "n"(N) : "memory");
}
__device__ __forceinline__ uint32_t smem_u32(const void* p) {
    uint32_t a;
    asm("{ .reg .u64 t; cvta.to.shared.u64 t, %1; cvt.u32.u64 %0, t; }" : "=r"(a) : "l"(p));
    return a;
}
// D += A*B, m16n8k16 fp16 inputs, fp32 accum
__device__ __forceinline__ void mma16(float* d, uint32_t a0, uint32_t a1, uint32_t a2,
                                      uint32_t a3, uint32_t b0, uint32_t b1) {
    asm volatile(
        "mma.sync.aligned.m16n8k16.row.col.f32.f16.f16.f32 "
        "{%0,%1,%2,%3},{%4,%5,%6,%7},{%8,%9},{%0,%1,%2,%3};"
        : "+f"(d[0]), "+f"(d[1]), "+f"(d[2]), "+f"(d[3])
        : "r"(a0), "r"(a1), "r"(a2), "r"(a3), "r"(b0), "r"(b1));
}
// permuted element index within 32-block (pair-level 4x4 transpose; involution)
__device__ __forceinline__ int pperm(int c) {
    const int p = (c & 31) >> 1;
    const int pp = ((p & 3) << 2) | (p >> 2);
    return (c & ~31) | (pp << 1) | (c & 1);
}

// ---------------- FP16 multi-pass NT GEMM via mma.sync (pair-permuted operands) ----------------
// C[m,n] = alpha * sum_k A[m,k]*B[n,k]. CTA 128x128, BK=32, 256 thr (2x4 warps).
// PASSES=3: AhBh + AlBh + AhBl.  PASSES=1: AhBh only.
// EPI=0: Cf = fp32*alpha (linear cols). EPI=1: Ch/Cl fp16 hi/lo (permuted cols).
// EPI=2: Ch fp16 hi only (permuted cols).
// causal: 0 none; 1 skip block if bn>bm; 2 Keff=min(K,(bm+1)*128), heavy-first bm remap.
static constexpr int GEMM_SMEM = 2 * 32768;   // 64 KB double buffer

template <int EPI, int PASSES>
__global__ __launch_bounds__(256, 2)
void mma_nt(const __half* __restrict__ Ahi, const __half* __restrict__ Alo,
            const __half* __restrict__ Bhi, const __half* __restrict__ Blo,
            float* __restrict__ Cf, __half* __restrict__ Ch, __half* __restrict__ Cl,
            int K, int lda, int ldb, int ldc,
            long long sA, long long sB, long long sC,
            float alpha, int causal)
{
    extern __shared__ char smc[];
    const int bn = blockIdx.x, bz = blockIdx.z;
    int bm = blockIdx.y;
    if (causal == 1 && bn > bm) return;
    if (causal == 2) bm = gridDim.y - 1 - bm;     // heavy tiles first
    int Keff = K;
    if (causal == 2) { int kl = (bm + 1) * 128; Keff = kl < K ? kl : K; }
    const int nk = Keff / 32;

    const __half* Ah = Ahi + (size_t)bz * sA;
    const __half* Al = (PASSES >= 2) ? Alo + (size_t)bz * sA : nullptr;
    const __half* Bh = Bhi + (size_t)bz * sB;
    const __half* Bl = (PASSES == 3) ? Blo + (size_t)bz * sB : nullptr;

    const int tid = threadIdx.x;
    const int lane = tid & 31, w = tid >> 5;
    const int wm = w & 1, wn = w >> 1;            // 2 (M) x 4 (N) warp grid
    const int gr = lane >> 2, tc = lane & 3;
    const uint32_t sbase = smem_u32(smc);

    // stage loader: arrays of [128][32] halves (64B rows); 512 16B-chunks each.
    auto load_stage = [&](int kt, int s) {
        const int k0 = kt * 32;
        const uint32_t dst = sbase + (uint32_t)s * 32768u;
#pragma unroll
        for (int t = 0; t < 2; t++) {
            const int idx = t * 256 + tid;         // 0..511
            const int row = idx >> 2, j = (idx & 3) * 8;
            const uint32_t off = (uint32_t)(row * 64 + j * 2);
            const size_t ga = (size_t)(bm * 128 + row) * lda + k0 + j;
            const size_t gb = (size_t)(bn * 128 + row) * ldb + k0 + j;
            cpa16(dst + off,           Ah + ga);
            if (PASSES >= 2) cpa16(dst + 8192u + off, Al + ga);
            cpa16(dst + 16384u + off,  Bh + gb);
            if (PASSES == 3) cpa16(dst + 24576u + off, Bl + gb);
        }
        cp_commit();
    };

    float acc[4][4][4];
#pragma unroll
    for (int i = 0; i < 4; i++)
#pragma unroll
        for (int j = 0; j < 4; j++)
#pragma unroll
            for (int r = 0; r < 4; r++) acc[i][j][r] = 0.f;

    load_stage(0, 0);

    const int rbA = (wm * 64 + gr) * 4 + tc;       // uint4 index of A frag row
    const int rbB = (wn * 32 + gr) * 4 + tc;

    for (int kt = 0; kt < nk; kt++) {
        const int s = kt & 1;
        cp_wait<0>();
        __syncthreads();                            // data(kt) visible; compute(kt-1) done
        if (kt + 1 < nk) load_stage(kt + 1, s ^ 1); // overlaps compute(kt)

        const uint4* S   = (const uint4*)(smc + s * 32768);
        const uint4* pAh = S;
        const uint4* pAl = S + 512;
        const uint4* pBh = S + 1024;
        const uint4* pBl = S + 1536;

        uint4 bh0 = pBh[rbB], bh1 = pBh[rbB + 32], bh2 = pBh[rbB + 64], bh3 = pBh[rbB + 96];

#pragma unroll
        for (int fm = 0; fm < 4; fm++) {
            const int ra = rbA + fm * 64;
            uint4 a0 = pAh[ra], a8 = pAh[ra + 32];
            uint4 l0, l8;
            if (PASSES >= 2) { l0 = pAl[ra]; l8 = pAl[ra + 32]; }
#pragma unroll
            for (int fn = 0; fn < 4; fn++) {
                const uint4 bh = fn == 0 ? bh0 : fn == 1 ? bh1 : fn == 2 ? bh2 : bh3;
                float* a = acc[fm][fn];
                mma16(a, a0.x, a8.x, a0.y, a8.y, bh.x, bh.y);
                if (PASSES >= 2) mma16(a, l0.x, l8.x, l0.y, l8.y, bh.x, bh.y);
                mma16(a, a0.z, a8.z, a0.w, a8.w, bh.z, bh.w);
                if (PASSES >= 2) mma16(a, l0.z, l8.z, l0.w, l8.w, bh.z, bh.w);
            }
        }

        if (PASSES == 3) {
            uint4 bl0 = pBl[rbB], bl1 = pBl[rbB + 32], bl2 = pBl[rbB + 64], bl3 = pBl[rbB + 96];
#pragma unroll
            for (int fm = 0; fm < 4; fm++) {
                const int ra = rbA + fm * 64;
                uint4 a0 = pAh[ra], a8 = pAh[ra + 32];
#pragma unroll
                for (int fn = 0; fn < 4; fn++) {
                    const uint4 bl = fn == 0 ? bl0 : fn == 1 ? bl1 : fn == 2 ? bl2 : bl3;
                    float* a = acc[fm][fn];
                    mma16(a, a0.x, a8.x, a0.y, a8.y, bl.x, bl.y);
                    mma16(a, a0.z, a8.z, a0.w, a8.w, bl.z, bl.w);
                }
            }
        }
    }

    // ---- epilogue ----
#pragma unroll
    for (int fm = 0; fm < 4; fm++) {
        const int r0 = bm * 128 + wm * 64 + fm * 16 + gr;
#pragma unroll
        for (int fn = 0; fn < 4; fn++) {
            const int c0 = bn * 128 + wn * 32 + fn * 8 + 2 * tc;
            const size_t b0 = (size_t)bz * sC + (size_t)r0 * ldc;
            const size_t b8 = b0 + (size_t)8 * ldc;
            const float* a = acc[fm][fn];
            if (EPI == 0) {
                *(float2*)(Cf + b0 + c0) = make_float2(a[0] * alpha, a[1] * alpha);
                *(float2*)(Cf + b8 + c0) = make_float2(a[2] * alpha, a[3] * alpha);
            } else {
                const int cp = pperm(c0);
                __half h0 = __float2half_rn(a[0]), h1 = __float2half_rn(a[1]);
                __half h2 = __float2half_rn(a[2]), h3 = __float2half_rn(a[3]);
                *(__half2*)(Ch + b0 + cp) = __halves2half2(h0, h1);
                *(__half2*)(Ch + b8 + cp) = __halves2half2(h2, h3);
                if (EPI == 1) {
                    *(__half2*)(Cl + b0 + cp) = __halves2half2(
                        __float2half_rn(a[0] - __half2float(h0)),
                        __float2half_rn(a[1] - __half2float(h1)));
                    *(__half2*)(Cl + b8 + cp) = __halves2half2(
                        __float2half_rn(a[2] - __half2float(h2)),
                        __float2half_rn(a[3] - __half2float(h3)));
                }
            }
        }
    }
}

// ---------------- elementwise fp16 split, pair-permuted layout ----------------
__global__ void split_kernel(const float* __restrict__ src,
                             __half* __restrict__ hi, __half* __restrict__ lo, int n8)
{
    const int i = blockIdx.x * blockDim.x + threadIdx.x;
    if (i >= n8) return;
    const int u = i & 3;
    const int blk = (i >> 2) * 32;
    uint32_t ho[4], lw[4];
#pragma unroll
    for (int b = 0; b < 4; b++) {
        const float2 v = *(const float2*)(src + blk + 8 * b + 2 * u);
        __half h0 = __float2half_rn(v.x), h1 = __float2half_rn(v.y);
        ho[b] = pack2(h0, h1);
        lw[b] = pack2(__float2half_rn(v.x - __half2float(h0)),
                      __float2half_rn(v.y - __half2float(h1)));
    }
    ((uint2*)(hi + blk))[u * 2 + 0] = make_uint2(ho[0], ho[1]);
    ((uint2*)(hi + blk))[u * 2 + 1] = make_uint2(ho[2], ho[3]);
    if (lo) {
        ((uint2*)(lo + blk))[u * 2 + 0] = make_uint2(lw[0], lw[1]);
        ((uint2*)(lo + blk))[u * 2 + 1] = make_uint2(lw[2], lw[3]);
    }
}

// ---------------- Mt split-K reduce + permuted fp16 hi/lo split ----------------
__global__ void mt_reduce_split(const float* __restrict__ p,
                                __half* __restrict__ hi, __half* __restrict__ lo, int n8)
{
    const int i = blockIdx.x * blockDim.x + threadIdx.x;
    if (i >= n8) return;
    const size_t CC = (size_t)C_ * C_;
    const int u = i & 3;
    const int blk = (i >> 2) * 32;
    uint32_t ho[4], lw[4];
#pragma unroll
    for (int b = 0; b < 4; b++) {
        const size_t o = (size_t)blk + 8 * b + 2 * u;
        float2 v0 = *(const float2*)(p + o);
        float2 v1 = *(const float2*)(p + CC + o);
        float2 v2 = *(const float2*)(p + 2 * CC + o);
        float2 v3 = *(const float2*)(p + 3 * CC + o);
        float x = (v0.x + v1.x) + (v2.x + v3.x);
        float y = (v0.y + v1.y) + (v2.y + v3.y);
        __half h0 = __float2half_rn(x), h1 = __float2half_rn(y);
        ho[b] = pack2(h0, h1);
        lw[b] = pack2(__float2half_rn(x - __half2float(h0)),
                      __float2half_rn(y - __half2float(h1)));
    }
    ((uint2*)(hi + blk))[u * 2 + 0] = make_uint2(ho[0], ho[1]);
    ((uint2*)(hi + blk))[u * 2 + 1] = make_uint2(ho[2], ho[3]);
    ((uint2*)(lo + blk))[u * 2 + 0] = make_uint2(lw[0], lw[1]);
    ((uint2*)(lo + blk))[u * 2 + 1] = make_uint2(lw[2], lw[3]);
}

// ---------------- fused dual transpose + fp16 split: W[H,C] -> Wt hi/lo [C,H] ----------------
__global__ __launch_bounds__(256)
void transpose_split2_kernel(const float* __restrict__ W0,
                             __half* __restrict__ t0h, __half* __restrict__ t0l,
                             const float* __restrict__ W1,
                             __half* __restrict__ t1h, __half* __restrict__ t1l,
                             int Hd, int Cd)
{
    const float* W = (blockIdx.z == 0) ? W0 : W1;
    __half* th = (blockIdx.z == 0) ? t0h : t1h;
    __half* tl = (blockIdx.z == 0) ? t0l : t1l;

    __shared__ float tile[64][33];
    const int c0 = blockIdx.x * 32, h0 = blockIdx.y * 64;
    const int tid = threadIdx.x;
    {
        const int lc = tid & 31;
        const int lh = tid >> 5;
#pragma unroll
        for (int i = 0; i < 8; i++)
            tile[lh + 8 * i][lc] = W[(size_t)(h0 + lh + 8 * i) * Cd + c0 + lc];
    }
    __syncthreads();
    const int lc = tid >> 3;
    const int lp = tid & 7;
#pragma unroll
    for (int i = 0; i < 4; i++) {
        const int p = lp + 8 * i;
        const int b = p >> 4;
        const int pin = p & 15;
        const int ppin = ((pin & 3) << 2) | (pin >> 2);
        const int hs = p * 2;
        const float v0 = tile[hs][lc], v1 = tile[hs + 1][lc];
        const __half h0_ = __float2half_rn(v0), h1_ = __float2half_rn(v1);
        const size_t o = (size_t)(c0 + lc) * Hd + h0 + b * 32 + ppin * 2;
        *(__half2*)(th + o) = __halves2half2(h0_, h1_);
        *(__half2*)(tl + o) = __halves2half2(__float2half_rn(v0 - __half2float(h0_)),
                                             __float2half_rn(v1 - __half2float(h1_)));
    }
}

// ---------------- single-sweep causal softmax + fp16 hi write (permuted cols) ----------------
__global__ __launch_bounds__(256)
void softmax_split_kernel(float* __restrict__ W, __half* __restrict__ Wh, int T)
{
    const long long row = blockIdx.x;
    const int t = (int)(row % T);
    float* p   = W  + row * (long long)T;
    __half* ph = Wh + row * (long long)T;
    const int n = t + 1;
    const int tid = threadIdx.x;
    const int base = tid * 8;

    __shared__ float red[8];

    float v[8];
    if (base + 7 < n) {
        float4 a = *(const float4*)(p + base);
        float4 b = *(const float4*)(p + base + 4);
        v[0] = a.x; v[1] = a.y; v[2] = a.z; v[3] = a.w;
        v[4] = b.x; v[5] = b.y; v[6] = b.z; v[7] = b.w;
    } else {
#pragma unroll
        for (int j = 0; j < 8; j++)
            v[j] = (base + j < n) ? p[base + j] : -3.4e38f;
    }

    float m = v[0];
#pragma unroll
    for (int j = 1; j < 8; j++) m = fmaxf(m, v[j]);
#pragma unroll
    for (int o = 16; o; o >>= 1) m = fmaxf(m, __shfl_xor_sync(0xffffffffu, m, o));
    if ((tid & 31) == 0) red[tid >> 5] = m;
    __syncthreads();
    if (tid < 32) {
        float mb = (tid < 8) ? red[tid] : -3.4e38f;
#pragma unroll
        for (int o = 4; o; o >>= 1) mb = fmaxf(mb, __shfl_xor_sync(0xffffffffu, mb, o));
        if (tid == 0) red[0] = mb;
    }
    __syncthreads();
    m = red[0];
    __syncthreads();

    float s = 0.f;
#pragma unroll
    for (int j = 0; j < 8; j++) {
        v[j] = (base + j < n) ? __expf(v[j] - m) : 0.f;
        s += v[j];
    }
#pragma unroll
    for (int o = 16; o; o >>= 1) s += __shfl_xor_sync(0xffffffffu, s, o);
    if ((tid & 31) == 0) red[tid >> 5] = s;
    __syncthreads();
    if (tid < 32) {
        float sb = (tid < 8) ? red[tid] : 0.f;
#pragma unroll
        for (int o = 4; o; o >>= 1) sb += __shfl_xor_sync(0xffffffffu, sb, o);
        if (tid == 0) red[0] = sb;
    }
    __syncthreads();
    const float inv = 1.f / red[0];

#pragma unroll
    for (int j = 0; j < 8; j++) v[j] *= inv;
    *(float4*)(p + base)     = make_float4(v[0], v[1], v[2], v[3]);
    *(float4*)(p + base + 4) = make_float4(v[4], v[5], v[6], v[7]);

    const int u = tid & 3;
    __half* phb = ph + (base & ~31);
#pragma unroll
    for (int b = 0; b < 4; b++) {
        *(__half2*)(phb + (b * 4 + u) * 2) =
            __halves2half2(__float2half_rn(v[2 * b]), __float2half_rn(v[2 * b + 1]));
    }
}

// ---------------- launch ----------------
extern "C" void kernel_launch(void* const* d_in, const int* in_sizes, int n_in,
                              void* d_out, int out_size)
{
    (void)in_sizes; (void)n_in; (void)out_size;
    const float* x  = (const float*)d_in[0];
    const float* Wk = (const float*)d_in[1];
    const float* Wq = (const float*)d_in[2];
    const float* Wv = (const float*)d_in[3];

    float* out = (float*)d_out;                      // [B, T, H]
    float* wei = out + (size_t)B_ * T_ * H_;         // [B, T, T]

    __half *xh, *xl, *wqth, *wqtl, *wkth, *wktl, *mth, *mtl, *uh, *ul, *wvh, *vth, *weih;
    float* mtp;
    cudaGetSymbolAddress((void**)&xh, g_xh);     cudaGetSymbolAddress((void**)&xl, g_xl);
    cudaGetSymbolAddress((void**)&wqth, g_wqth); cudaGetSymbolAddress((void**)&wqtl, g_wqtl);
    cudaGetSymbolAddress((void**)&wkth, g_wkth); cudaGetSymbolAddress((void**)&wktl, g_wktl);
    cudaGetSymbolAddress((void**)&mtp, g_mtp);
    cudaGetSymbolAddress((void**)&mth, g_mth);   cudaGetSymbolAddress((void**)&mtl, g_mtl);
    cudaGetSymbolAddress((void**)&uh, g_uh);     cudaGetSymbolAddress((void**)&ul, g_ul);
    cudaGetSymbolAddress((void**)&wvh, g_wvh);
    cudaGetSymbolAddress((void**)&vth, g_vth);
    cudaGetSymbolAddress((void**)&weih, g_weih);

    static cudaStream_t s2 = nullptr;
    static cudaEvent_t evX = nullptr, evV = nullptr;
    if (!s2) {
        cudaStreamCreateWithFlags(&s2, cudaStreamNonBlocking);
        cudaEventCreateWithFlags(&evX, cudaEventDisableTiming);
        cudaEventCreateWithFlags(&evV, cudaEventDisableTiming);
        cudaFuncSetAttribute(mma_nt<0,3>, cudaFuncAttributeMaxDynamicSharedMemorySize, GEMM_SMEM);
        cudaFuncSetAttribute(mma_nt<1,3>, cudaFuncAttributeMaxDynamicSharedMemorySize, GEMM_SMEM);
        cudaFuncSetAttribute(mma_nt<2,1>, cudaFuncAttributeMaxDynamicSharedMemorySize, GEMM_SMEM);
        cudaFuncSetAttribute(mma_nt<0,1>, cudaFuncAttributeMaxDynamicSharedMemorySize, GEMM_SMEM);
    }

    const dim3 blk(256);

    // ---- main stream: split x (needed by both chains), then fork ----
    {
        const int n8x = (B_ * T_ * C_) / 8;
        split_kernel<<<(n8x + 255) / 256, 256>>>(x, xh, xl, n8x);
    }
    cudaEventRecord(evX, 0);

    // ---- side stream (chain B): split Wv -> v GEMM ----
    cudaStreamWaitEvent(s2, evX, 0);
    {
        const int n8w = (H_ * C_) / 8;
        split_kernel<<<(n8w + 255) / 256, 256, 0, s2>>>(Wv, wvh, nullptr, n8w);
        const dim3 g(T_ / 128, H_ / 128, B_);
        mma_nt<2,1><<<g, blk, GEMM_SMEM, s2>>>(wvh, nullptr, xh, nullptr, nullptr, vth, nullptr,
                                               C_, C_, C_, T_,
                                               0, (long long)T_ * C_, (long long)H_ * T_, 1.f, 0);
    }
    cudaEventRecord(evV, s2);

    // ---- main stream (chain A): transposes -> Mt -> reduce -> u -> logits -> softmax ----
    {
        const dim3 gt(C_ / 32, H_ / 64, 2);
        transpose_split2_kernel<<<gt, blk>>>(Wq, wqth, wqtl, Wk, wkth, wktl, H_, C_);
    }
    {
        const dim3 g(C_ / 128, C_ / 128, 4);
        mma_nt<0,3><<<g, blk, GEMM_SMEM>>>(wkth, wktl, wqth, wqtl, mtp, nullptr, nullptr,
                                           256, H_, H_, C_,
                                           256, 256, (long long)C_ * C_, 1.f, 0);
        mt_reduce_split<<<(C_ * C_ / 8 + 255) / 256, 256>>>(mtp, mth, mtl, C_ * C_ / 8);
    }
    {
        const dim3 g(C_ / 128, (B_ * T_) / 128, 1);
        mma_nt<1,3><<<g, blk, GEMM_SMEM>>>(xh, xl, mth, mtl, nullptr, uh, ul,
                                           C_, C_, C_, C_, 0, 0, 0, 1.f, 0);
    }
    {
        const dim3 g(T_ / 128, T_ / 128, B_);
        mma_nt<0,3><<<g, blk, GEMM_SMEM>>>(uh, ul, xh, xl, wei, nullptr, nullptr,
                                           C_, C_, C_, T_,
                                           (long long)T_ * C_, (long long)T_ * C_,
                                           (long long)T_ * T_, 0.03125f, 1);
    }
    softmax_split_kernel<<<B_ * T_, 256>>>(wei, weih, T_);

    // ---- join: out-GEMM needs v (chain B) and wei (chain A) ----
    cudaStreamWaitEvent(0, evV, 0);
    {
        const dim3 g(H_ / 128, T_ / 128, B_);
        mma_nt<0,1><<<g, blk, GEMM_SMEM>>>(weih, nullptr, vth, nullptr, out, nullptr, nullptr,
                                           T_, T_, T_, H_,
                                           (long long)T_ * T_, (long long)H_ * T_,
                                           (long long)T_ * H_, 1.f, 2);
    }
}

// round 16
// speedup vs baseline: 1.3394x; 1.0493x over previous
#include <cuda_runtime.h>
#include <cuda_fp16.h>
#include <cstdint>

// ---------------- problem shape ----------------
static constexpr int B_ = 8;
static constexpr int T_ = 2048;
static constexpr int C_ = 1024;
static constexpr int H_ = 1024;

// ---------------- scratch (__device__ globals) ----------------
__device__ __half g_xh[(size_t)B_ * T_ * C_];
__device__ __half g_xl[(size_t)B_ * T_ * C_];
__device__ __half g_wqth[(size_t)C_ * H_];   // Wq^T [C,H], permuted along H
__device__ __half g_wqtl[(size_t)C_ * H_];
__device__ __half g_wkth[(size_t)C_ * H_];
__device__ __half g_wktl[(size_t)C_ * H_];
__device__ float  g_mtp[(size_t)4 * C_ * C_];  // Mt split-K partials (fp32)
__device__ __half g_mth[(size_t)C_ * C_];      // Mt hi/lo, permuted along c
__device__ __half g_mtl[(size_t)C_ * C_];
__device__ __half g_uh[(size_t)B_ * T_ * C_];  // u = x·M, permuted along c'
__device__ __half g_ul[(size_t)B_ * T_ * C_];
__device__ __half g_wvh[(size_t)H_ * C_];
__device__ __half g_vth[(size_t)B_ * H_ * T_];   // v^T [b][h][t], hi only
__device__ __half g_weih[(size_t)B_ * T_ * T_];  // wei fp16 hi only

// ---------------- helpers ----------------
__device__ __forceinline__ uint32_t pack2(__half a, __half b) {
    __half2 h2 = __halves2half2(a, b);
    return *reinterpret_cast<uint32_t*>(&h2);
}
__device__ __forceinline__ void cpa16(uint32_t dst, const void* src) {
    asm volatile("cp.async.cg.shared.global [%0], [%1], 16;" :: "r"(dst), "l"(src));
}
__device__ __forceinline__ void cp_commit() {
    asm volatile("cp.async.commit_group;" ::: "memory");
}
template <int N>
__device__ __forceinline__ void cp_wait() {
    asm volatile("cp.async.wait_group %0;" :: "n"(N) : "memory");
}
__device__ __forceinline__ uint32_t smem_u32(const void* p) {
    uint32_t a;
    asm("{ .reg .u64 t; cvta.to.shared.u64 t, %1; cvt.u32.u64 %0, t; }" : "=r"(a) : "l"(p));
    return a;
}
__device__ __forceinline__ void mma16(float* d, uint32_t a0, uint32_t a1, uint32_t a2,
                                      uint32_t a3, uint32_t b0, uint32_t b1) {
    asm volatile(
        "mma.sync.aligned.m16n8k16.row.col.f32.f16.f16.f32 "
        "{%0,%1,%2,%3},{%4,%5,%6,%7},{%8,%9},{%0,%1,%2,%3};"
        : "+f"(d[0]), "+f"(d[1]), "+f"(d[2]), "+f"(d[3])
        : "r"(a0), "r"(a1), "r"(a2), "r"(a3), "r"(b0), "r"(b1));
}
__device__ __forceinline__ int pperm(int c) {
    const int p = (c & 31) >> 1;
    const int pp = ((p & 3) << 2) | (p >> 2);
    return (c & ~31) | (pp << 1) | (c & 1);
}

// ---------------- FP16 multi-pass NT GEMM via mma.sync (pair-permuted operands) ----------------
static constexpr int GEMM_SMEM = 2 * 32768;   // 64 KB double buffer

template <int EPI, int PASSES>
__global__ __launch_bounds__(256, 2)
void mma_nt(const __half* __restrict__ Ahi, const __half* __restrict__ Alo,
            const __half* __restrict__ Bhi, const __half* __restrict__ Blo,
            float* __restrict__ Cf, __half* __restrict__ Ch, __half* __restrict__ Cl,
            int K, int lda, int ldb, int ldc,
            long long sA, long long sB, long long sC,
            float alpha, int causal)
{
    extern __shared__ char smc[];
    const int bn = blockIdx.x, bz = blockIdx.z;
    int bm = blockIdx.y;
    if (causal == 1 && bn > bm) return;
    if (causal == 2) bm = gridDim.y - 1 - bm;     // heavy tiles first
    int Keff = K;
    if (causal == 2) { int kl = (bm + 1) * 128; Keff = kl < K ? kl : K; }
    const int nk = Keff / 32;

    const __half* Ah = Ahi + (size_t)bz * sA;
    const __half* Al = (PASSES >= 2) ? Alo + (size_t)bz * sA : nullptr;
    const __half* Bh = Bhi + (size_t)bz * sB;
    const __half* Bl = (PASSES == 3) ? Blo + (size_t)bz * sB : nullptr;

    const int tid = threadIdx.x;
    const int lane = tid & 31, w = tid >> 5;
    const int wm = w & 1, wn = w >> 1;            // 2 (M) x 4 (N) warp grid
    const int gr = lane >> 2, tc = lane & 3;
    const uint32_t sbase = smem_u32(smc);

    auto load_stage = [&](int kt, int s) {
        const int k0 = kt * 32;
        const uint32_t dst = sbase + (uint32_t)s * 32768u;
#pragma unroll
        for (int t = 0; t < 2; t++) {
            const int idx = t * 256 + tid;         // 0..511
            const int row = idx >> 2, j = (idx & 3) * 8;
            const uint32_t off = (uint32_t)(row * 64 + j * 2);
            const size_t ga = (size_t)(bm * 128 + row) * lda + k0 + j;
            const size_t gb = (size_t)(bn * 128 + row) * ldb + k0 + j;
            cpa16(dst + off,           Ah + ga);
            if (PASSES >= 2) cpa16(dst + 8192u + off, Al + ga);
            cpa16(dst + 16384u + off,  Bh + gb);
            if (PASSES == 3) cpa16(dst + 24576u + off, Bl + gb);
        }
        cp_commit();
    };

    float acc[4][4][4];
#pragma unroll
    for (int i = 0; i < 4; i++)
#pragma unroll
        for (int j = 0; j < 4; j++)
#pragma unroll
            for (int r = 0; r < 4; r++) acc[i][j][r] = 0.f;

    load_stage(0, 0);

    const int rbA = (wm * 64 + gr) * 4 + tc;
    const int rbB = (wn * 32 + gr) * 4 + tc;

    for (int kt = 0; kt < nk; kt++) {
        const int s = kt & 1;
        cp_wait<0>();
        __syncthreads();
        if (kt + 1 < nk) load_stage(kt + 1, s ^ 1);

        const uint4* S   = (const uint4*)(smc + s * 32768);
        const uint4* pAh = S;
        const uint4* pAl = S + 512;
        const uint4* pBh = S + 1024;
        const uint4* pBl = S + 1536;

        uint4 bh0 = pBh[rbB], bh1 = pBh[rbB + 32], bh2 = pBh[rbB + 64], bh3 = pBh[rbB + 96];

#pragma unroll
        for (int fm = 0; fm < 4; fm++) {
            const int ra = rbA + fm * 64;
            uint4 a0 = pAh[ra], a8 = pAh[ra + 32];
            uint4 l0, l8;
            if (PASSES >= 2) { l0 = pAl[ra]; l8 = pAl[ra + 32]; }
#pragma unroll
            for (int fn = 0; fn < 4; fn++) {
                const uint4 bh = fn == 0 ? bh0 : fn == 1 ? bh1 : fn == 2 ? bh2 : bh3;
                float* a = acc[fm][fn];
                mma16(a, a0.x, a8.x, a0.y, a8.y, bh.x, bh.y);
                if (PASSES >= 2) mma16(a, l0.x, l8.x, l0.y, l8.y, bh.x, bh.y);
                mma16(a, a0.z, a8.z, a0.w, a8.w, bh.z, bh.w);
                if (PASSES >= 2) mma16(a, l0.z, l8.z, l0.w, l8.w, bh.z, bh.w);
            }
        }

        if (PASSES == 3) {
            uint4 bl0 = pBl[rbB], bl1 = pBl[rbB + 32], bl2 = pBl[rbB + 64], bl3 = pBl[rbB + 96];
#pragma unroll
            for (int fm = 0; fm < 4; fm++) {
                const int ra = rbA + fm * 64;
                uint4 a0 = pAh[ra], a8 = pAh[ra + 32];
#pragma unroll
                for (int fn = 0; fn < 4; fn++) {
                    const uint4 bl = fn == 0 ? bl0 : fn == 1 ? bl1 : fn == 2 ? bl2 : bl3;
                    float* a = acc[fm][fn];
                    mma16(a, a0.x, a8.x, a0.y, a8.y, bl.x, bl.y);
                    mma16(a, a0.z, a8.z, a0.w, a8.w, bl.z, bl.w);
                }
            }
        }
    }

#pragma unroll
    for (int fm = 0; fm < 4; fm++) {
        const int r0 = bm * 128 + wm * 64 + fm * 16 + gr;
#pragma unroll
        for (int fn = 0; fn < 4; fn++) {
            const int c0 = bn * 128 + wn * 32 + fn * 8 + 2 * tc;
            const size_t b0 = (size_t)bz * sC + (size_t)r0 * ldc;
            const size_t b8 = b0 + (size_t)8 * ldc;
            const float* a = acc[fm][fn];
            if (EPI == 0) {
                *(float2*)(Cf + b0 + c0) = make_float2(a[0] * alpha, a[1] * alpha);
                *(float2*)(Cf + b8 + c0) = make_float2(a[2] * alpha, a[3] * alpha);
            } else {
                const int cp = pperm(c0);
                __half h0 = __float2half_rn(a[0]), h1 = __float2half_rn(a[1]);
                __half h2 = __float2half_rn(a[2]), h3 = __float2half_rn(a[3]);
                *(__half2*)(Ch + b0 + cp) = __halves2half2(h0, h1);
                *(__half2*)(Ch + b8 + cp) = __halves2half2(h2, h3);
                if (EPI == 1) {
                    *(__half2*)(Cl + b0 + cp) = __halves2half2(
                        __float2half_rn(a[0] - __half2float(h0)),
                        __float2half_rn(a[1] - __half2float(h1)));
                    *(__half2*)(Cl + b8 + cp) = __halves2half2(
                        __float2half_rn(a[2] - __half2float(h2)),
                        __float2half_rn(a[3] - __half2float(h3)));
                }
            }
        }
    }
}

// ---------------- elementwise fp16 split, pair-permuted layout ----------------
__global__ void split_kernel(const float* __restrict__ src,
                             __half* __restrict__ hi, __half* __restrict__ lo, int n8)
{
    const int i = blockIdx.x * blockDim.x + threadIdx.x;
    if (i >= n8) return;
    const int u = i & 3;
    const int blk = (i >> 2) * 32;
    uint32_t ho[4], lw[4];
#pragma unroll
    for (int b = 0; b < 4; b++) {
        const float2 v = *(const float2*)(src + blk + 8 * b + 2 * u);
        __half h0 = __float2half_rn(v.x), h1 = __float2half_rn(v.y);
        ho[b] = pack2(h0, h1);
        lw[b] = pack2(__float2half_rn(v.x - __half2float(h0)),
                      __float2half_rn(v.y - __half2float(h1)));
    }
    ((uint2*)(hi + blk))[u * 2 + 0] = make_uint2(ho[0], ho[1]);
    ((uint2*)(hi + blk))[u * 2 + 1] = make_uint2(ho[2], ho[3]);
    if (lo) {
        ((uint2*)(lo + blk))[u * 2 + 0] = make_uint2(lw[0], lw[1]);
        ((uint2*)(lo + blk))[u * 2 + 1] = make_uint2(lw[2], lw[3]);
    }
}

// ---------------- Mt split-K reduce + permuted fp16 hi/lo split ----------------
__global__ void mt_reduce_split(const float* __restrict__ p,
                                __half* __restrict__ hi, __half* __restrict__ lo, int n8)
{
    const int i = blockIdx.x * blockDim.x + threadIdx.x;
    if (i >= n8) return;
    const size_t CC = (size_t)C_ * C_;
    const int u = i & 3;
    const int blk = (i >> 2) * 32;
    uint32_t ho[4], lw[4];
#pragma unroll
    for (int b = 0; b < 4; b++) {
        const size_t o = (size_t)blk + 8 * b + 2 * u;
        float2 v0 = *(const float2*)(p + o);
        float2 v1 = *(const float2*)(p + CC + o);
        float2 v2 = *(const float2*)(p + 2 * CC + o);
        float2 v3 = *(const float2*)(p + 3 * CC + o);
        float x = (v0.x + v1.x) + (v2.x + v3.x);
        float y = (v0.y + v1.y) + (v2.y + v3.y);
        __half h0 = __float2half_rn(x), h1 = __float2half_rn(y);
        ho[b] = pack2(h0, h1);
        lw[b] = pack2(__float2half_rn(x - __half2float(h0)),
                      __float2half_rn(y - __half2float(h1)));
    }
    ((uint2*)(hi + blk))[u * 2 + 0] = make_uint2(ho[0], ho[1]);
    ((uint2*)(hi + blk))[u * 2 + 1] = make_uint2(ho[2], ho[3]);
    ((uint2*)(lo + blk))[u * 2 + 0] = make_uint2(lw[0], lw[1]);
    ((uint2*)(lo + blk))[u * 2 + 1] = make_uint2(lw[2], lw[3]);
}

// ---------------- fused dual transpose + fp16 split ----------------
__global__ __launch_bounds__(256)
void transpose_split2_kernel(const float* __restrict__ W0,
                             __half* __restrict__ t0h, __half* __restrict__ t0l,
                             const float* __restrict__ W1,
                             __half* __restrict__ t1h, __half* __restrict__ t1l,
                             int Hd, int Cd)
{
    const float* W = (blockIdx.z == 0) ? W0 : W1;
    __half* th = (blockIdx.z == 0) ? t0h : t1h;
    __half* tl = (blockIdx.z == 0) ? t0l : t1l;

    __shared__ float tile[64][33];
    const int c0 = blockIdx.x * 32, h0 = blockIdx.y * 64;
    const int tid = threadIdx.x;
    {
        const int lc = tid & 31;
        const int lh = tid >> 5;
#pragma unroll
        for (int i = 0; i < 8; i++)
            tile[lh + 8 * i][lc] = W[(size_t)(h0 + lh + 8 * i) * Cd + c0 + lc];
    }
    __syncthreads();
    const int lc = tid >> 3;
    const int lp = tid & 7;
#pragma unroll
    for (int i = 0; i < 4; i++) {
        const int p = lp + 8 * i;
        const int b = p >> 4;
        const int pin = p & 15;
        const int ppin = ((pin & 3) << 2) | (pin >> 2);
        const int hs = p * 2;
        const float v0 = tile[hs][lc], v1 = tile[hs + 1][lc];
        const __half h0_ = __float2half_rn(v0), h1_ = __float2half_rn(v1);
        const size_t o = (size_t)(c0 + lc) * Hd + h0 + b * 32 + ppin * 2;
        *(__half2*)(th + o) = __halves2half2(h0_, h1_);
        *(__half2*)(tl + o) = __halves2half2(__float2half_rn(v0 - __half2float(h0_)),
                                             __float2half_rn(v1 - __half2float(h1_)));
    }
}

// ---------------- single-sweep causal softmax + fp16 hi write (permuted cols) ----------------
__global__ __launch_bounds__(256)
void softmax_split_kernel(float* __restrict__ W, __half* __restrict__ Wh, int T)
{
    const long long row = blockIdx.x;
    const int t = (int)(row % T);
    float* p   = W  + row * (long long)T;
    __half* ph = Wh + row * (long long)T;
    const int n = t + 1;
    const int tid = threadIdx.x;
    const int base = tid * 8;

    __shared__ float red[8];

    float v[8];
    if (base + 7 < n) {
        float4 a = *(const float4*)(p + base);
        float4 b = *(const float4*)(p + base + 4);
        v[0] = a.x; v[1] = a.y; v[2] = a.z; v[3] = a.w;
        v[4] = b.x; v[5] = b.y; v[6] = b.z; v[7] = b.w;
    } else {
#pragma unroll
        for (int j = 0; j < 8; j++)
            v[j] = (base + j < n) ? p[base + j] : -3.4e38f;
    }

    float m = v[0];
#pragma unroll
    for (int j = 1; j < 8; j++) m = fmaxf(m, v[j]);
#pragma unroll
    for (int o = 16; o; o >>= 1) m = fmaxf(m, __shfl_xor_sync(0xffffffffu, m, o));
    if ((tid & 31) == 0) red[tid >> 5] = m;
    __syncthreads();
    if (tid < 32) {
        float mb = (tid < 8) ? red[tid] : -3.4e38f;
#pragma unroll
        for (int o = 4; o; o >>= 1) mb = fmaxf(mb, __shfl_xor_sync(0xffffffffu, mb, o));
        if (tid == 0) red[0] = mb;
    }
    __syncthreads();
    m = red[0];
    __syncthreads();

    float s = 0.f;
#pragma unroll
    for (int j = 0; j < 8; j++) {
        v[j] = (base + j < n) ? __expf(v[j] - m) : 0.f;
        s += v[j];
    }
#pragma unroll
    for (int o = 16; o; o >>= 1) s += __shfl_xor_sync(0xffffffffu, s, o);
    if ((tid & 31) == 0) red[tid >> 5] = s;
    __syncthreads();
    if (tid < 32) {
        float sb = (tid < 8) ? red[tid] : 0.f;
#pragma unroll
        for (int o = 4; o; o >>= 1) sb += __shfl_xor_sync(0xffffffffu, sb, o);
        if (tid == 0) red[0] = sb;
    }
    __syncthreads();
    const float inv = 1.f / red[0];

#pragma unroll
    for (int j = 0; j < 8; j++) v[j] *= inv;
    *(float4*)(p + base)     = make_float4(v[0], v[1], v[2], v[3]);
    *(float4*)(p + base + 4) = make_float4(v[4], v[5], v[6], v[7]);

    const int u = tid & 3;
    __half* phb = ph + (base & ~31);
#pragma unroll
    for (int b = 0; b < 4; b++) {
        *(__half2*)(phb + (b * 4 + u) * 2) =
            __halves2half2(__float2half_rn(v[2 * b]), __float2half_rn(v[2 * b + 1]));
    }
}

// ---------------- launch ----------------
extern "C" void kernel_launch(void* const* d_in, const int* in_sizes, int n_in,
                              void* d_out, int out_size)
{
    (void)in_sizes; (void)n_in; (void)out_size;
    const float* x  = (const float*)d_in[0];
    const float* Wk = (const float*)d_in[1];
    const float* Wq = (const float*)d_in[2];
    const float* Wv = (const float*)d_in[3];

    float* out = (float*)d_out;                      // [B, T, H]
    float* wei = out + (size_t)B_ * T_ * H_;         // [B, T, T]

    __half *xh, *xl, *wqth, *wqtl, *wkth, *wktl, *mth, *mtl, *uh, *ul, *wvh, *vth, *weih;
    float* mtp;
    cudaGetSymbolAddress((void**)&xh, g_xh);     cudaGetSymbolAddress((void**)&xl, g_xl);
    cudaGetSymbolAddress((void**)&wqth, g_wqth); cudaGetSymbolAddress((void**)&wqtl, g_wqtl);
    cudaGetSymbolAddress((void**)&wkth, g_wkth); cudaGetSymbolAddress((void**)&wktl, g_wktl);
    cudaGetSymbolAddress((void**)&mtp, g_mtp);
    cudaGetSymbolAddress((void**)&mth, g_mth);   cudaGetSymbolAddress((void**)&mtl, g_mtl);
    cudaGetSymbolAddress((void**)&uh, g_uh);     cudaGetSymbolAddress((void**)&ul, g_ul);
    cudaGetSymbolAddress((void**)&wvh, g_wvh);
    cudaGetSymbolAddress((void**)&vth, g_vth);
    cudaGetSymbolAddress((void**)&weih, g_weih);

    static cudaStream_t sMt = nullptr, sV = nullptr, sB2 = nullptr;
    static cudaEvent_t evX = nullptr, evMt = nullptr, evV = nullptr, evU = nullptr, evB = nullptr;
    if (!sMt) {
        cudaStreamCreateWithFlags(&sMt, cudaStreamNonBlocking);
        cudaStreamCreateWithFlags(&sV,  cudaStreamNonBlocking);
        cudaStreamCreateWithFlags(&sB2, cudaStreamNonBlocking);
        cudaEventCreateWithFlags(&evX,  cudaEventDisableTiming);
        cudaEventCreateWithFlags(&evMt, cudaEventDisableTiming);
        cudaEventCreateWithFlags(&evV,  cudaEventDisableTiming);
        cudaEventCreateWithFlags(&evU,  cudaEventDisableTiming);
        cudaEventCreateWithFlags(&evB,  cudaEventDisableTiming);
        cudaFuncSetAttribute(mma_nt<0,3>, cudaFuncAttributeMaxDynamicSharedMemorySize, GEMM_SMEM);
        cudaFuncSetAttribute(mma_nt<1,3>, cudaFuncAttributeMaxDynamicSharedMemorySize, GEMM_SMEM);
        cudaFuncSetAttribute(mma_nt<2,1>, cudaFuncAttributeMaxDynamicSharedMemorySize, GEMM_SMEM);
        cudaFuncSetAttribute(mma_nt<0,1>, cudaFuncAttributeMaxDynamicSharedMemorySize, GEMM_SMEM);
    }

    const dim3 blk(256);
    const long long sTT = (long long)T_ * T_;
    const long long sTC = (long long)T_ * C_;
    const long long sHT = (long long)H_ * T_;
    const long long sTH = (long long)T_ * H_;

    // Fork point: record origin state so side streams are captured as branches.
    cudaEventRecord(evX, 0);

    // ---- stream sMt: transposes -> Mt -> reduce  (independent of x) ----
    cudaStreamWaitEvent(sMt, evX, 0);
    {
        const dim3 gt(C_ / 32, H_ / 64, 2);
        transpose_split2_kernel<<<gt, blk, 0, sMt>>>(Wq, wqth, wqtl, Wk, wkth, wktl, H_, C_);
        const dim3 g(C_ / 128, C_ / 128, 4);
        mma_nt<0,3><<<g, blk, GEMM_SMEM, sMt>>>(wkth, wktl, wqth, wqtl, mtp, nullptr, nullptr,
                                                256, H_, H_, C_,
                                                256, 256, (long long)C_ * C_, 1.f, 0);
        mt_reduce_split<<<(C_ * C_ / 8 + 255) / 256, 256, 0, sMt>>>(mtp, mth, mtl, C_ * C_ / 8);
    }
    cudaEventRecord(evMt, sMt);

    // ---- origin: split x ----
    {
        const int n8x = (B_ * T_ * C_) / 8;
        split_kernel<<<(n8x + 255) / 256, 256>>>(x, xh, xl, n8x);
    }
    cudaEventRecord(evX, 0);

    // ---- stream sV: split Wv -> v GEMM (needs split x) ----
    cudaStreamWaitEvent(sV, evX, 0);
    {
        const int n8w = (H_ * C_) / 8;
        split_kernel<<<(n8w + 255) / 256, 256, 0, sV>>>(Wv, wvh, nullptr, n8w);
        const dim3 g(T_ / 128, H_ / 128, B_);
        mma_nt<2,1><<<g, blk, GEMM_SMEM, sV>>>(wvh, nullptr, xh, nullptr, nullptr, vth, nullptr,
                                               C_, C_, C_, T_, 0, sTC, sHT, 1.f, 0);
    }
    cudaEventRecord(evV, sV);

    // ---- origin: u = x·Mt (needs split x + Mt) ----
    cudaStreamWaitEvent(0, evMt, 0);
    {
        const dim3 g(C_ / 128, (B_ * T_) / 128, 1);
        mma_nt<1,3><<<g, blk, GEMM_SMEM>>>(xh, xl, mth, mtl, nullptr, uh, ul,
                                           C_, C_, C_, C_, 0, 0, 0, 1.f, 0);
    }
    cudaEventRecord(evU, 0);

    // ---- batch-half pipelines: logits -> softmax -> out ----
    // Half A (batches 0..3) on origin; half B (batches 4..7) on sB2.
    cudaStreamWaitEvent(sB2, evU, 0);
    const int HB = B_ / 2;   // 4 batches per half

    // half B
    {
        const dim3 g(T_ / 128, T_ / 128, HB);
        mma_nt<0,3><<<g, blk, GEMM_SMEM, sB2>>>(uh + HB * sTC, ul + HB * sTC,
                                                xh + HB * sTC, xl + HB * sTC,
                                                wei + HB * sTT, nullptr, nullptr,
                                                C_, C_, C_, T_, sTC, sTC, sTT, 0.03125f, 1);
        softmax_split_kernel<<<HB * T_, 256, 0, sB2>>>(wei + HB * sTT, weih + HB * sTT, T_);
        cudaStreamWaitEvent(sB2, evV, 0);
        const dim3 go(H_ / 128, T_ / 128, HB);
        mma_nt<0,1><<<go, blk, GEMM_SMEM, sB2>>>(weih + HB * sTT, nullptr,
                                                 vth + HB * sHT, nullptr,
                                                 out + HB * sTH, nullptr, nullptr,
                                                 T_, T_, T_, H_, sTT, sHT, sTH, 1.f, 2);
    }
    cudaEventRecord(evB, sB2);

    // half A
    {
        const dim3 g(T_ / 128, T_ / 128, HB);
        mma_nt<0,3><<<g, blk, GEMM_SMEM>>>(uh, ul, xh, xl, wei, nullptr, nullptr,
                                           C_, C_, C_, T_, sTC, sTC, sTT, 0.03125f, 1);
        softmax_split_kernel<<<HB * T_, 256>>>(wei, weih, T_);
        cudaStreamWaitEvent(0, evV, 0);
        const dim3 go(H_ / 128, T_ / 128, HB);
        mma_nt<0,1><<<go, blk, GEMM_SMEM>>>(weih, nullptr, vth, nullptr, out, nullptr, nullptr,
                                            T_, T_, T_, H_, sTT, sHT, sTH, 1.f, 2);
    }

    // ---- join all side streams back into origin ----
    cudaStreamWaitEvent(0, evB, 0);
}